// round 10
// baseline (speedup 1.0000x reference)
#include <cuda_runtime.h>
#include <math.h>
#include <stdint.h>

#define BB 4
#define LL 2048
#define DD 1024
#define HH 16
#define HD 64

// Q prescale: 1/sqrt(64) * log2(e) -> softmax in exp2 domain.
#define QSCALE 0.1803368801111204f

// Scratch (device globals). All fp16 payloads stored as packed uint32 words.
__device__ float    g_qkv[(size_t)BB * LL * 3 * DD];       // fp16 words [M][1536]
__device__ float    g_att[(size_t)BB * LL * DD];           // fp16 words [M][512]
__device__ uint32_t g_xt  [(size_t)BB * LL * DD];          // x fp16 words [M][512]
__device__ uint32_t g_wq  [(size_t)3 * DD * DD];           // Wqkv fp16 words [3072][512]
__device__ uint32_t g_wo  [(size_t)DD * DD];               // Wout fp16 words [1024][512]
__device__ uint32_t g_vt  [(size_t)BB * HH * HD * (LL/2)]; // V^T fp16 words [(b,h,hd)][1024]

// pos8 on word index within an 8-word (16-elem) group: i<4 -> 2i, else 2i-7.
__device__ __host__ __forceinline__ int pos8(int i) {
    return (i < 4) ? (i << 1) : ((i << 1) - 7);
}

__device__ __forceinline__ uint32_t pack_f16x2(float lo, float hi) {
    uint32_t r;
    asm("cvt.rn.f16x2.f32 %0, %1, %2;" : "=r"(r) : "f"(hi), "f"(lo));
    return r;
}

__device__ __forceinline__ void cp_async16(uint32_t smem_addr, const void* gptr) {
    asm volatile("cp.async.cg.shared.global [%0], [%1], 16;\n"
                 :: "r"(smem_addr), "l"(gptr));
}
__device__ __forceinline__ void cp_commit() {
    asm volatile("cp.async.commit_group;\n" ::: "memory");
}
template <int N>
__device__ __forceinline__ void cp_wait() {
    asm volatile("cp.async.wait_group %0;\n" :: "n"(N) : "memory");
}

// m16n8k16 f16 mma, f32 acc.
__device__ __forceinline__ void mma_f16(float* d, const uint32_t* a,
                                        uint32_t b0, uint32_t b1) {
    asm volatile(
        "mma.sync.aligned.m16n8k16.row.col.f32.f16.f16.f32 "
        "{%0,%1,%2,%3}, {%4,%5,%6,%7}, {%8,%9}, {%0,%1,%2,%3};\n"
        : "+f"(d[0]), "+f"(d[1]), "+f"(d[2]), "+f"(d[3])
        : "r"(a[0]), "r"(a[1]), "r"(a[2]), "r"(a[3]), "r"(b0), "r"(b1));
}

// ---------------------------------------------------------------------------
// Prepass: fp32 -> fp16 words, word index pos8-permuted within 16-elem groups.
// ---------------------------------------------------------------------------
__global__ void perm_f16_kernel(const float* __restrict__ in,
                                uint32_t* __restrict__ out, int rows, int cols) {
    int gid = blockIdx.x * blockDim.x + threadIdx.x;
    const int gpr = cols >> 4;
    if (gid >= rows * gpr) return;
    const int r = gid / gpr;
    const int gk = gid - r * gpr;
    const float* ip = in + (size_t)r * cols + gk * 16;
    uint32_t* op = out + (size_t)r * (cols >> 1) + gk * 8;
    float e[16];
#pragma unroll
    for (int i = 0; i < 16; i += 4) {
        float4 v = *(const float4*)(ip + i);
        e[i] = v.x; e[i + 1] = v.y; e[i + 2] = v.z; e[i + 3] = v.w;
    }
#pragma unroll
    for (int i = 0; i < 8; i++)
        op[pos8(i)] = pack_f16x2(e[2 * i], e[2 * i + 1]);
}

// ---------------------------------------------------------------------------
// fp16 GEMM (mma.sync m16n8k16), C = A @ W^T + bias.
// Block 128x128, kTile 32 words (64 elems), 4 warps (2x2), warp 64x64.
// 3-stage cp.async; PADDED stride-36 rows -> every fragment LDS.64 address is
// base_reg + compile-time immediate (no per-load ALU), banks 4qr+2qc+ks
// conflict-free. Register double-buffered fragments.
// MODE 0: fp32 out + bias. MODE 1: fp16 words out, Q cols scaled, Q/K word-perm.
// ---------------------------------------------------------------------------
#define GST 36
#define GBUF (128 * GST)                 // words per operand per stage
#define SMEM_GEMM (3 * GBUF * 2 * 4)     // 110592 B

template <int MODE>
__global__ __launch_bounds__(128) void gemm_f16(
    const uint32_t* __restrict__ A, const uint32_t* __restrict__ W,
    const float* __restrict__ bias, float* __restrict__ C,
    int M, int N, int Kw)
{
    extern __shared__ uint32_t gsm[];   // As[3][GBUF] | Ws[3][GBUF]

    const int tid = threadIdx.x;
    const int lane = tid & 31;
    const int ww = tid >> 5;
    const int wr = ww >> 1;
    const int wc = ww & 1;
    const int qr = lane >> 2;
    const int qc = lane & 3;
    const int bm = blockIdx.y * 128;
    const int bn = blockIdx.x * 128;

    float acc[4][8][4];
#pragma unroll
    for (int i = 0; i < 4; i++)
#pragma unroll
        for (int j = 0; j < 8; j++)
#pragma unroll
            for (int c = 0; c < 4; c++) acc[i][j][c] = 0.0f;

    const uint32_t sm_base = (uint32_t)__cvta_generic_to_shared(gsm);
    const int nkt = Kw / 32;

    auto stage = [&](int kt_idx, int s) {
#pragma unroll
        for (int i = 0; i < 8; i++) {       // A: 1024 chunks of 16B
            const int q = i * 128 + tid;
            const int r = q >> 3, c = q & 7;
            cp_async16(sm_base + (uint32_t)((s * GBUF + r * GST + c * 4) * 4),
                       A + (size_t)(bm + r) * Kw + kt_idx * 32 + c * 4);
        }
#pragma unroll
        for (int i = 0; i < 8; i++) {       // W: 1024 chunks
            const int q = i * 128 + tid;
            const int r = q >> 3, c = q & 7;
            cp_async16(sm_base + (uint32_t)((3 * GBUF + s * GBUF + r * GST + c * 4) * 4),
                       W + (size_t)(bn + r) * Kw + kt_idx * 32 + c * 4);
        }
        cp_commit();
    };

    stage(0, 0);
    stage(1, 1);

    int s = 0;
    for (int kt = 0; kt < nkt; kt++) {
        if (kt + 1 < nkt) cp_wait<1>();
        else              cp_wait<0>();
        __syncthreads();
        if (kt + 2 < nkt) {
            int s2 = s + 2; if (s2 >= 3) s2 -= 3;
            stage(kt + 2, s2);
        }

        // per-stage, per-thread fragment base pointers (linear addressing)
        const uint32_t* As = gsm + s * GBUF;
        const uint32_t* Ws = gsm + 3 * GBUF + s * GBUF;
        const uint32_t* arow[4][2];
        const uint32_t* nrow[8];
#pragma unroll
        for (int mi = 0; mi < 4; mi++) {
            const int mr = wr * 64 + mi * 16 + qr;
            arow[mi][0] = &As[mr * GST + 2 * qc];
            arow[mi][1] = &As[(mr + 8) * GST + 2 * qc];
        }
#pragma unroll
        for (int ni = 0; ni < 8; ni++) {
            const int nr = wc * 64 + ni * 8 + qr;
            nrow[ni] = &Ws[nr * GST + 2 * qc];
        }

        uint32_t aa[2][4][4], bb[2][8][2];

#define LDFRAG(buf, ks)                                                        \
        do {                                                                   \
            _Pragma("unroll")                                                  \
            for (int mi = 0; mi < 4; mi++) {                                   \
                const uint2 u0 = *(const uint2*)(arow[mi][0] + (ks));          \
                const uint2 u1 = *(const uint2*)(arow[mi][1] + (ks));          \
                aa[buf][mi][0] = u0.x; aa[buf][mi][1] = u1.x;                  \
                aa[buf][mi][2] = u0.y; aa[buf][mi][3] = u1.y;                  \
            }                                                                  \
            _Pragma("unroll")                                                  \
            for (int ni = 0; ni < 8; ni++) {                                   \
                const uint2 v = *(const uint2*)(nrow[ni] + (ks));              \
                bb[buf][ni][0] = v.x; bb[buf][ni][1] = v.y;                    \
            }                                                                  \
        } while (0)

        LDFRAG(0, 0);
#pragma unroll
        for (int st = 0; st < 4; st++) {
            const int cur = st & 1;
            if (st < 3) {
                const int nxt = (st + 1) & 1;
                switch (st) {
                    case 0: LDFRAG(nxt, 8);  break;
                    case 1: LDFRAG(nxt, 16); break;
                    default: LDFRAG(nxt, 24); break;
                }
            }
#pragma unroll
            for (int mi = 0; mi < 4; mi++)
#pragma unroll
                for (int ni = 0; ni < 8; ni++)
                    mma_f16(acc[mi][ni], aa[cur][mi], bb[cur][ni][0], bb[cur][ni][1]);
        }
#undef LDFRAG

        s++; if (s == 3) s = 0;
    }

#pragma unroll
    for (int mi = 0; mi < 4; mi++) {
        const int row = bm + wr * 64 + mi * 16 + qr;
#pragma unroll
        for (int ni = 0; ni < 8; ni++) {
            const int col = bn + wc * 64 + ni * 8 + qc * 2;
            const float b0 = bias[col], b1 = bias[col + 1];
            float* d = acc[mi][ni];
            float v00 = d[0] + b0, v01 = d[1] + b1;
            float v10 = d[2] + b0, v11 = d[3] + b1;
            if (MODE == 1) {
                const float sc = (col < DD) ? QSCALE : 1.0f;
                v00 *= sc; v01 *= sc; v10 *= sc; v11 *= sc;
                const int w = col >> 1;
                const int wp = (col < 2 * DD) ? ((w & ~7) | pos8(w & 7)) : w;
                uint32_t* C32 = (uint32_t*)C;
                C32[(size_t)row * (N >> 1) + wp]       = pack_f16x2(v00, v01);
                C32[(size_t)(row + 8) * (N >> 1) + wp] = pack_f16x2(v10, v11);
            } else {
                *(float2*)(C + (size_t)row * N + col)       = make_float2(v00, v01);
                *(float2*)(C + (size_t)(row + 8) * N + col) = make_float2(v10, v11);
            }
        }
    }
}

// ---------------------------------------------------------------------------
// V transpose: qkv V section -> g_vt [(b,h,hd)][seq-pairs], seq-words pos8'd.
// ---------------------------------------------------------------------------
__global__ __launch_bounds__(128) void transpose_v_kernel(
    const float* __restrict__ qkvf, uint32_t* __restrict__ vt)
{
    __shared__ uint32_t ts[64][33];
    const int bh = blockIdx.x;
    const int b = bh >> 4, h = bh & 15;
    const int sc = blockIdx.y;
    const int tid = threadIdx.x;

    const uint32_t* vg = (const uint32_t*)qkvf
        + ((size_t)(b * LL + sc * 64)) * 1536 + 1024 + h * 32;
#pragma unroll
    for (int i = 0; i < 16; i++) {
        const int q = i * 128 + tid;
        const int r = q >> 5, c = q & 31;
        ts[r][c] = vg[(size_t)r * 1536 + c];
    }
    __syncthreads();

#pragma unroll
    for (int i = 0; i < 16; i++) {
        const int q = i * 128 + tid;
        const int hd = q >> 5, sw = q & 31;
        const uint32_t w0 = ts[2 * sw][hd >> 1];
        const uint32_t w1 = ts[2 * sw + 1][hd >> 1];
        const uint32_t sh = (hd & 1) * 16;
        const uint32_t val = ((w0 >> sh) & 0xffffu) | (((w1 >> sh) & 0xffffu) << 16);
        const int swp = (sw & ~7) | pos8(sw & 7);
        vt[((size_t)(bh * 64 + hd)) * (LL / 2) + sc * 32 + swp] = val;
    }
}

// ---------------------------------------------------------------------------
// Causal flash attention, fp16 mma (unchanged from R8/R9, passing).
// ---------------------------------------------------------------------------
#define AST 40
#define TILE_WORDS (64 * AST)
#define OFF_K0 0
#define OFF_V0 (2 * TILE_WORDS)
#define SMEM_ATTN (4 * TILE_WORDS * 4)   // 40 KB

__global__ __launch_bounds__(128) void attn_f16_kernel(
    const float* __restrict__ qkvf, const uint32_t* __restrict__ vt,
    float* __restrict__ outf)
{
    extern __shared__ uint32_t sm[];
    const uint32_t* qkv = (const uint32_t*)qkvf;
    uint32_t* att = (uint32_t*)outf;

    const int qt = gridDim.x - 1 - blockIdx.x;
    const int h  = blockIdx.y;
    const int b  = blockIdx.z;

    const int tid = threadIdx.x;
    const int lane = tid & 31;
    const int wid = tid >> 5;
    const int qr = lane >> 2;
    const int qc = lane & 3;

    const uint32_t sm_base = (uint32_t)__cvta_generic_to_shared(sm);

    uint32_t qa[2][4][4];
    const uint32_t* qb = qkv + ((size_t)(b * LL + qt * 128 + wid * 32)) * 1536 + h * 32;
#pragma unroll
    for (int mi = 0; mi < 2; mi++)
#pragma unroll
        for (int ks = 0; ks < 4; ks++) {
            const size_t r0 = (size_t)(mi * 16 + qr) * 1536;
            const uint2 u0 = *(const uint2*)(qb + r0 + ks * 8 + 2 * qc);
            const uint2 u1 = *(const uint2*)(qb + r0 + 8 * 1536 + ks * 8 + 2 * qc);
            qa[mi][ks][0] = u0.x; qa[mi][ks][1] = u1.x;
            qa[mi][ks][2] = u0.y; qa[mi][ks][3] = u1.y;
        }

    float o[2][8][4];
    float m[2][2], l[2][2];
#pragma unroll
    for (int mi = 0; mi < 2; mi++) {
        m[mi][0] = m[mi][1] = -INFINITY;
        l[mi][0] = l[mi][1] = 0.0f;
#pragma unroll
        for (int j = 0; j < 8; j++)
#pragma unroll
            for (int c = 0; c < 4; c++) o[mi][j][c] = 0.0f;
    }

    const int jmax = 2 * qt + 1;
    const uint32_t* vtb = vt + ((size_t)((b * HH + h) * 64)) * (LL / 2);

    auto stage = [&](int jt, int s) {
        const uint32_t* kg = qkv + ((size_t)(b * LL + jt * 64)) * 1536 + 512 + h * 32;
#pragma unroll
        for (int i = 0; i < 4; i++) {
            const int q = i * 128 + tid;
            const int r = q >> 3, c = q & 7;
            cp_async16(sm_base + (uint32_t)((OFF_K0 + s * TILE_WORDS + r * AST + c * 4) * 4),
                       kg + (size_t)r * 1536 + c * 4);
        }
#pragma unroll
        for (int i = 0; i < 4; i++) {
            const int q = i * 128 + tid;
            const int r = q >> 3, c = q & 7;
            cp_async16(sm_base + (uint32_t)((OFF_V0 + s * TILE_WORDS + r * AST + c * 4) * 4),
                       vtb + (size_t)r * (LL / 2) + jt * 32 + c * 4);
        }
        cp_commit();
    };

    stage(0, 0);

    for (int jt = 0; jt <= jmax; jt++) {
        const int s = jt & 1;
        __syncthreads();
        if (jt + 1 <= jmax) { stage(jt + 1, s ^ 1); cp_wait<1>(); }
        else                { cp_wait<0>(); }
        __syncthreads();

        const uint32_t* Ks = sm + OFF_K0 + s * TILE_WORDS;
        const uint32_t* Vs = sm + OFF_V0 + s * TILE_WORDS;

        const int wrow_min = qt * 128 + wid * 32;
        const bool tile_dead = (jt * 64) > (wrow_min + 31);

        if (!tile_dead) {
            float sreg[2][8][4];
#pragma unroll
            for (int mi = 0; mi < 2; mi++)
#pragma unroll
                for (int j = 0; j < 8; j++)
#pragma unroll
                    for (int c = 0; c < 4; c++) sreg[mi][j][c] = 0.0f;

#pragma unroll
            for (int ks = 0; ks < 4; ks++) {
#pragma unroll
                for (int j = 0; j < 8; j++) {
                    const uint2 kk = *(const uint2*)&Ks[(j * 8 + qr) * AST + ks * 8 + 2 * qc];
                    mma_f16(sreg[0][j], qa[0][ks], kk.x, kk.y);
                    mma_f16(sreg[1][j], qa[1][ks], kk.x, kk.y);
                }
            }

            if ((jt + 1) * 64 - 1 > wrow_min) {
#pragma unroll
                for (int mi = 0; mi < 2; mi++) {
                    const int r0 = wrow_min + mi * 16 + qr;
#pragma unroll
                    for (int j = 0; j < 8; j++) {
                        const int c0 = jt * 64 + j * 8 + qc * 2;
                        if (c0     > r0)     sreg[mi][j][0] = -INFINITY;
                        if (c0 + 1 > r0)     sreg[mi][j][1] = -INFINITY;
                        if (c0     > r0 + 8) sreg[mi][j][2] = -INFINITY;
                        if (c0 + 1 > r0 + 8) sreg[mi][j][3] = -INFINITY;
                    }
                }
            }

#pragma unroll
            for (int mi = 0; mi < 2; mi++) {
                float mt0 = -INFINITY, mt1 = -INFINITY;
#pragma unroll
                for (int j = 0; j < 8; j++) {
                    mt0 = fmaxf(mt0, fmaxf(sreg[mi][j][0], sreg[mi][j][1]));
                    mt1 = fmaxf(mt1, fmaxf(sreg[mi][j][2], sreg[mi][j][3]));
                }
#pragma unroll
                for (int off = 1; off <= 2; off <<= 1) {
                    mt0 = fmaxf(mt0, __shfl_xor_sync(0xffffffffu, mt0, off));
                    mt1 = fmaxf(mt1, __shfl_xor_sync(0xffffffffu, mt1, off));
                }
                const float mn0 = fmaxf(m[mi][0], mt0);
                const float mn1 = fmaxf(m[mi][1], mt1);
                const float al0 = exp2f(m[mi][0] - mn0);
                const float al1 = exp2f(m[mi][1] - mn1);
                m[mi][0] = mn0; m[mi][1] = mn1;
                float rs0 = 0.0f, rs1 = 0.0f;
#pragma unroll
                for (int j = 0; j < 8; j++) {
                    sreg[mi][j][0] = exp2f(sreg[mi][j][0] - mn0);
                    sreg[mi][j][1] = exp2f(sreg[mi][j][1] - mn0);
                    sreg[mi][j][2] = exp2f(sreg[mi][j][2] - mn1);
                    sreg[mi][j][3] = exp2f(sreg[mi][j][3] - mn1);
                    rs0 += sreg[mi][j][0] + sreg[mi][j][1];
                    rs1 += sreg[mi][j][2] + sreg[mi][j][3];
                }
#pragma unroll
                for (int off = 1; off <= 2; off <<= 1) {
                    rs0 += __shfl_xor_sync(0xffffffffu, rs0, off);
                    rs1 += __shfl_xor_sync(0xffffffffu, rs1, off);
                }
                l[mi][0] = l[mi][0] * al0 + rs0;
                l[mi][1] = l[mi][1] * al1 + rs1;
#pragma unroll
                for (int j = 0; j < 8; j++) {
                    o[mi][j][0] *= al0; o[mi][j][1] *= al0;
                    o[mi][j][2] *= al1; o[mi][j][3] *= al1;
                }
            }

#pragma unroll
            for (int ks = 0; ks < 4; ks++) {
                uint32_t pa0[4], pa1[4];
                pa0[0] = pack_f16x2(sreg[0][2 * ks][0],     sreg[0][2 * ks][1]);
                pa0[1] = pack_f16x2(sreg[0][2 * ks][2],     sreg[0][2 * ks][3]);
                pa0[2] = pack_f16x2(sreg[0][2 * ks + 1][0], sreg[0][2 * ks + 1][1]);
                pa0[3] = pack_f16x2(sreg[0][2 * ks + 1][2], sreg[0][2 * ks + 1][3]);
                pa1[0] = pack_f16x2(sreg[1][2 * ks][0],     sreg[1][2 * ks][1]);
                pa1[1] = pack_f16x2(sreg[1][2 * ks][2],     sreg[1][2 * ks][3]);
                pa1[2] = pack_f16x2(sreg[1][2 * ks + 1][0], sreg[1][2 * ks + 1][1]);
                pa1[3] = pack_f16x2(sreg[1][2 * ks + 1][2], sreg[1][2 * ks + 1][3]);
#pragma unroll
                for (int j = 0; j < 8; j++) {
                    const uint2 vv = *(const uint2*)&Vs[(j * 8 + qr) * AST + ks * 8 + 2 * qc];
                    mma_f16(o[0][j], pa0, vv.x, vv.y);
                    mma_f16(o[1][j], pa1, vv.x, vv.y);
                }
            }
        }
    }

    const int orow0 = b * LL + qt * 128 + wid * 32;
#pragma unroll
    for (int mi = 0; mi < 2; mi++) {
        const float inv0 = 1.0f / l[mi][0];
        const float inv1 = 1.0f / l[mi][1];
        const size_t r0 = (size_t)(orow0 + mi * 16 + qr) * 512;
#pragma unroll
        for (int j = 0; j < 8; j++) {
            const int wl = j * 4 + qc;
            const int wp = h * 32 + ((wl & ~7) | pos8(wl & 7));
            att[r0 + wp]             = pack_f16x2(o[mi][j][0] * inv0, o[mi][j][1] * inv0);
            att[r0 + 8 * 512 + wp]   = pack_f16x2(o[mi][j][2] * inv1, o[mi][j][3] * inv1);
        }
    }
}

// ---------------------------------------------------------------------------
extern "C" void kernel_launch(void* const* d_in, const int* in_sizes, int n_in,
                              void* d_out, int out_size)
{
    const float* x    = (const float*)d_in[0];
    const float* Wqkv = (const float*)d_in[1];
    const float* bqkv = (const float*)d_in[2];
    const float* Wout = (const float*)d_in[3];
    const float* bout = (const float*)d_in[4];
    float* outp = (float*)d_out;

    float *qkv = nullptr, *att = nullptr;
    uint32_t *xt = nullptr, *wq = nullptr, *wo = nullptr, *vt = nullptr;
    cudaGetSymbolAddress((void**)&qkv, g_qkv);
    cudaGetSymbolAddress((void**)&att, g_att);
    cudaGetSymbolAddress((void**)&xt, g_xt);
    cudaGetSymbolAddress((void**)&wq, g_wq);
    cudaGetSymbolAddress((void**)&wo, g_wo);
    cudaGetSymbolAddress((void**)&vt, g_vt);

    static bool attr_set = false;
    if (!attr_set) {
        cudaFuncSetAttribute(attn_f16_kernel,
                             cudaFuncAttributeMaxDynamicSharedMemorySize, SMEM_ATTN);
        cudaFuncSetAttribute(gemm_f16<0>,
                             cudaFuncAttributeMaxDynamicSharedMemorySize, SMEM_GEMM);
        cudaFuncSetAttribute(gemm_f16<1>,
                             cudaFuncAttributeMaxDynamicSharedMemorySize, SMEM_GEMM);
        attr_set = true;
    }

    const int M = BB * LL;   // 8192
    const int Kw = DD / 2;   // 512 words

    // prepass: fp32 -> fp16 words, pos8 word-perm (same perm on both operands)
    {
        int ng = (M * DD) / 16;
        perm_f16_kernel<<<(ng + 255) / 256, 256>>>(x, xt, M, DD);
        ng = (3 * DD * DD) / 16;
        perm_f16_kernel<<<(ng + 255) / 256, 256>>>(Wqkv, wq, 3 * DD, DD);
        ng = (DD * DD) / 16;
        perm_f16_kernel<<<(ng + 255) / 256, 256>>>(Wout, wo, DD, DD);
    }

    // 1) QKV projection (fp16 words out; Q scaled; Q,K word-perm'd, V linear)
    {
        dim3 grid((3 * DD) / 128, M / 128);
        gemm_f16<1><<<grid, 128, SMEM_GEMM>>>(xt, wq, bqkv, qkv, M, 3 * DD, Kw);
    }

    // 1b) V transpose -> [(b,h,hd)][seq-pairs]
    {
        dim3 grid(BB * HH, LL / 64);
        transpose_v_kernel<<<grid, 128>>>(qkv, vt);
    }

    // 2) causal attention
    {
        dim3 grid(LL / 128, HH, BB);
        attn_f16_kernel<<<grid, 128, SMEM_ATTN>>>(qkv, vt, att);
    }

    // 3) output projection (fp32 out)
    {
        dim3 grid(DD / 128, M / 128);
        gemm_f16<0><<<grid, 128, SMEM_GEMM>>>((const uint32_t*)att, wo, bout, outp,
                                              M, DD, Kw);
    }
}

// round 11
// speedup vs baseline: 1.0039x; 1.0039x over previous
#include <cuda_runtime.h>
#include <math.h>
#include <stdint.h>

#define BB 4
#define LL 2048
#define DD 1024
#define HH 16
#define HD 64

// Q prescale: 1/sqrt(64) * log2(e) -> softmax in exp2 domain.
#define QSCALE 0.1803368801111204f

// Scratch (device globals). All fp16 payloads stored as packed uint32 words.
__device__ float    g_qkv[(size_t)BB * LL * 3 * DD];       // fp16 words [M][1536]
__device__ float    g_att[(size_t)BB * LL * DD];           // fp16 words [M][512]
__device__ uint32_t g_xt  [(size_t)BB * LL * DD];          // x fp16 words [M][512]
__device__ uint32_t g_wq  [(size_t)3 * DD * DD];           // Wqkv fp16 words [3072][512]
__device__ uint32_t g_wo  [(size_t)DD * DD];               // Wout fp16 words [1024][512]
__device__ uint32_t g_vt  [(size_t)BB * HH * HD * (LL/2)]; // V^T fp16 words [(b,h,hd)][1024]

// pos8 on word index within an 8-word group (attention-internal layout).
__device__ __host__ __forceinline__ int pos8(int i) {
    return (i < 4) ? (i << 1) : ((i << 1) - 7);
}
// perm32 on word index within a 32-word (64-elem) k-group (GEMM operand layout):
// thread qc's fragment words for two adjacent k16-steps become 16B-contiguous.
__device__ __host__ __forceinline__ int perm32(int v) {
    const int t = v >> 3;          // k16-step 0..3
    const int w = v & 7;
    const int qcp = w & 3;         // word-within-step slot
    const int hi = w >> 2;         // 0: b0-word, 1: b1-word
    const int half = t >> 1;       // step pair
    const int g = t & 1;           // step within pair
    return half * 16 + qcp * 4 + g * 2 + hi;
}

__device__ __forceinline__ uint32_t pack_f16x2(float lo, float hi) {
    uint32_t r;
    asm("cvt.rn.f16x2.f32 %0, %1, %2;" : "=r"(r) : "f"(hi), "f"(lo));
    return r;
}

__device__ __forceinline__ void cp_async16(uint32_t smem_addr, const void* gptr) {
    asm volatile("cp.async.cg.shared.global [%0], [%1], 16;\n"
                 :: "r"(smem_addr), "l"(gptr));
}
__device__ __forceinline__ void cp_commit() {
    asm volatile("cp.async.commit_group;\n" ::: "memory");
}
template <int N>
__device__ __forceinline__ void cp_wait() {
    asm volatile("cp.async.wait_group %0;\n" :: "n"(N) : "memory");
}

// m16n8k16 f16 mma, f32 acc.
__device__ __forceinline__ void mma_f16(float* d, const uint32_t* a,
                                        uint32_t b0, uint32_t b1) {
    asm volatile(
        "mma.sync.aligned.m16n8k16.row.col.f32.f16.f16.f32 "
        "{%0,%1,%2,%3}, {%4,%5,%6,%7}, {%8,%9}, {%0,%1,%2,%3};\n"
        : "+f"(d[0]), "+f"(d[1]), "+f"(d[2]), "+f"(d[3])
        : "r"(a[0]), "r"(a[1]), "r"(a[2]), "r"(a[3]), "r"(b0), "r"(b1));
}

// ---------------------------------------------------------------------------
// Prepass: fp32 -> fp16 words, perm32 word layout within 32-word k-groups.
// One thread per 32 elements (16 words).
// ---------------------------------------------------------------------------
__global__ void perm_f16_kernel(const float* __restrict__ in,
                                uint32_t* __restrict__ out, int rows, int cols) {
    int gid = blockIdx.x * blockDim.x + threadIdx.x;
    const int gpr = cols >> 5;
    if (gid >= rows * gpr) return;
    const int r = gid / gpr;
    const int gk = gid - r * gpr;
    const float* ip = in + (size_t)r * cols + gk * 32;
    uint32_t* op = out + (size_t)r * (cols >> 1) + gk * 16;
    float e[32];
#pragma unroll
    for (int i = 0; i < 32; i += 4) {
        float4 v = *(const float4*)(ip + i);
        e[i] = v.x; e[i + 1] = v.y; e[i + 2] = v.z; e[i + 3] = v.w;
    }
#pragma unroll
    for (int v = 0; v < 16; v++)
        op[perm32(v)] = pack_f16x2(e[2 * v], e[2 * v + 1]);
}

// ---------------------------------------------------------------------------
// fp16 GEMM (mma.sync m16n8k16), C = A @ W^T + bias.
// Block 128x128, kTile 32 words (64 elems), 4 warps (2x2), warp 64x64.
// 3-stage cp.async. Operands perm32-laid: smem per stage per operand is two
// [128 rows x 16 words] half-tiles; each fragment pair (two k16-steps) is one
// LDS.128 at base+immediate. 16B-chunk index = (4*row + qc) mod 8 -> conflict-
// free per 8-lane phase. 32 LDS.128 + 128 HMMA per warp per ktile.
// MODE 0: fp32 out + bias. MODE 1: fp16 words out, Q cols scaled, Q/K pos8 for
//         attention, V linear.
// ---------------------------------------------------------------------------
#define HBUF (128 * 16)              // words per half-tile
#define GBUF (2 * HBUF)              // words per operand per stage
#define SMEM_GEMM (3 * GBUF * 2 * 4) // 98304 B

template <int MODE>
__global__ __launch_bounds__(128) void gemm_f16(
    const uint32_t* __restrict__ A, const uint32_t* __restrict__ W,
    const float* __restrict__ bias, float* __restrict__ C,
    int M, int N, int Kw)
{
    extern __shared__ uint32_t gsm[];   // As[3][GBUF] | Ws[3][GBUF]

    const int tid = threadIdx.x;
    const int lane = tid & 31;
    const int ww = tid >> 5;
    const int wr = ww >> 1;
    const int wc = ww & 1;
    const int qr = lane >> 2;
    const int qc = lane & 3;
    const int bm = blockIdx.y * 128;
    const int bn = blockIdx.x * 128;

    float acc[4][8][4];
#pragma unroll
    for (int i = 0; i < 4; i++)
#pragma unroll
        for (int j = 0; j < 8; j++)
#pragma unroll
            for (int c = 0; c < 4; c++) acc[i][j][c] = 0.0f;

    const uint32_t sm_base = (uint32_t)__cvta_generic_to_shared(gsm);
    const int nkt = Kw / 32;

    auto stage = [&](int kt_idx, int s) {
#pragma unroll
        for (int i = 0; i < 8; i++) {       // A: 1024 chunks of 16B
            const int q = i * 128 + tid;
            const int r = q >> 3, c = q & 7;
            const int off = s * GBUF + (c >> 2) * HBUF + r * 16 + (c & 3) * 4;
            cp_async16(sm_base + (uint32_t)(off * 4),
                       A + (size_t)(bm + r) * Kw + kt_idx * 32 + c * 4);
        }
#pragma unroll
        for (int i = 0; i < 8; i++) {       // W: 1024 chunks
            const int q = i * 128 + tid;
            const int r = q >> 3, c = q & 7;
            const int off = 3 * GBUF + s * GBUF + (c >> 2) * HBUF + r * 16 + (c & 3) * 4;
            cp_async16(sm_base + (uint32_t)(off * 4),
                       W + (size_t)(bn + r) * Kw + kt_idx * 32 + c * 4);
        }
        cp_commit();
    };

    stage(0, 0);
    stage(1, 1);

    int s = 0;
    for (int kt = 0; kt < nkt; kt++) {
        if (kt + 1 < nkt) cp_wait<1>();
        else              cp_wait<0>();
        __syncthreads();
        if (kt + 2 < nkt) {
            int s2 = s + 2; if (s2 >= 3) s2 -= 3;
            stage(kt + 2, s2);
        }

        const uint32_t* As = gsm + s * GBUF;
        const uint32_t* Ws = gsm + 3 * GBUF + s * GBUF;

#pragma unroll
        for (int half = 0; half < 2; half++) {
            const uint32_t* Ah = As + half * HBUF + (wr * 64 + qr) * 16 + 4 * qc;
            const uint32_t* Wh = Ws + half * HBUF + (wc * 64 + qr) * 16 + 4 * qc;

            uint4 au[4][2], bu[8];
#pragma unroll
            for (int mi = 0; mi < 4; mi++) {
                au[mi][0] = *(const uint4*)(Ah + mi * 256);          // row mi*16+qr
                au[mi][1] = *(const uint4*)(Ah + mi * 256 + 128);    // row +8
            }
#pragma unroll
            for (int ni = 0; ni < 8; ni++)
                bu[ni] = *(const uint4*)(Wh + ni * 128);             // row ni*8+qr

            // k16-step g=0 (.x/.y), then g=1 (.z/.w)
#pragma unroll
            for (int mi = 0; mi < 4; mi++) {
                uint32_t a0[4] = { au[mi][0].x, au[mi][1].x, au[mi][0].y, au[mi][1].y };
#pragma unroll
                for (int ni = 0; ni < 8; ni++)
                    mma_f16(acc[mi][ni], a0, bu[ni].x, bu[ni].y);
            }
#pragma unroll
            for (int mi = 0; mi < 4; mi++) {
                uint32_t a1[4] = { au[mi][0].z, au[mi][1].z, au[mi][0].w, au[mi][1].w };
#pragma unroll
                for (int ni = 0; ni < 8; ni++)
                    mma_f16(acc[mi][ni], a1, bu[ni].z, bu[ni].w);
            }
        }

        s++; if (s == 3) s = 0;
    }

#pragma unroll
    for (int mi = 0; mi < 4; mi++) {
        const int row = bm + wr * 64 + mi * 16 + qr;
#pragma unroll
        for (int ni = 0; ni < 8; ni++) {
            const int col = bn + wc * 64 + ni * 8 + qc * 2;
            const float b0 = bias[col], b1 = bias[col + 1];
            float* d = acc[mi][ni];
            float v00 = d[0] + b0, v01 = d[1] + b1;
            float v10 = d[2] + b0, v11 = d[3] + b1;
            if (MODE == 1) {
                const float sc = (col < DD) ? QSCALE : 1.0f;
                v00 *= sc; v01 *= sc; v10 *= sc; v11 *= sc;
                const int w = col >> 1;
                // Q/K: pos8 word layout (attention consumes it); V: linear.
                const int wp = (col < 2 * DD) ? ((w & ~7) | pos8(w & 7)) : w;
                uint32_t* C32 = (uint32_t*)C;
                C32[(size_t)row * (N >> 1) + wp]       = pack_f16x2(v00, v01);
                C32[(size_t)(row + 8) * (N >> 1) + wp] = pack_f16x2(v10, v11);
            } else {
                *(float2*)(C + (size_t)row * N + col)       = make_float2(v00, v01);
                *(float2*)(C + (size_t)(row + 8) * N + col) = make_float2(v10, v11);
            }
        }
    }
}

// ---------------------------------------------------------------------------
// V transpose: qkv V section -> g_vt [(b,h,hd)][seq-pairs], seq-words pos8'd.
// ---------------------------------------------------------------------------
__global__ __launch_bounds__(128) void transpose_v_kernel(
    const float* __restrict__ qkvf, uint32_t* __restrict__ vt)
{
    __shared__ uint32_t ts[64][33];
    const int bh = blockIdx.x;
    const int b = bh >> 4, h = bh & 15;
    const int sc = blockIdx.y;
    const int tid = threadIdx.x;

    const uint32_t* vg = (const uint32_t*)qkvf
        + ((size_t)(b * LL + sc * 64)) * 1536 + 1024 + h * 32;
#pragma unroll
    for (int i = 0; i < 16; i++) {
        const int q = i * 128 + tid;
        const int r = q >> 5, c = q & 31;
        ts[r][c] = vg[(size_t)r * 1536 + c];
    }
    __syncthreads();

#pragma unroll
    for (int i = 0; i < 16; i++) {
        const int q = i * 128 + tid;
        const int hd = q >> 5, sw = q & 31;
        const uint32_t w0 = ts[2 * sw][hd >> 1];
        const uint32_t w1 = ts[2 * sw + 1][hd >> 1];
        const uint32_t sh = (hd & 1) * 16;
        const uint32_t val = ((w0 >> sh) & 0xffffu) | (((w1 >> sh) & 0xffffu) << 16);
        const int swp = (sw & ~7) | pos8(sw & 7);
        vt[((size_t)(bh * 64 + hd)) * (LL / 2) + sc * 32 + swp] = val;
    }
}

// ---------------------------------------------------------------------------
// Causal flash attention, fp16 mma (R8/R9 proven). Only the epilogue word
// permutation changes: att is a GEMM0 A-operand -> perm32 layout.
// ---------------------------------------------------------------------------
#define AST 40
#define TILE_WORDS (64 * AST)
#define OFF_K0 0
#define OFF_V0 (2 * TILE_WORDS)
#define SMEM_ATTN (4 * TILE_WORDS * 4)   // 40 KB

__global__ __launch_bounds__(128) void attn_f16_kernel(
    const float* __restrict__ qkvf, const uint32_t* __restrict__ vt,
    float* __restrict__ outf)
{
    extern __shared__ uint32_t sm[];
    const uint32_t* qkv = (const uint32_t*)qkvf;
    uint32_t* att = (uint32_t*)outf;

    const int qt = gridDim.x - 1 - blockIdx.x;
    const int h  = blockIdx.y;
    const int b  = blockIdx.z;

    const int tid = threadIdx.x;
    const int lane = tid & 31;
    const int wid = tid >> 5;
    const int qr = lane >> 2;
    const int qc = lane & 3;

    const uint32_t sm_base = (uint32_t)__cvta_generic_to_shared(sm);

    uint32_t qa[2][4][4];
    const uint32_t* qb = qkv + ((size_t)(b * LL + qt * 128 + wid * 32)) * 1536 + h * 32;
#pragma unroll
    for (int mi = 0; mi < 2; mi++)
#pragma unroll
        for (int ks = 0; ks < 4; ks++) {
            const size_t r0 = (size_t)(mi * 16 + qr) * 1536;
            const uint2 u0 = *(const uint2*)(qb + r0 + ks * 8 + 2 * qc);
            const uint2 u1 = *(const uint2*)(qb + r0 + 8 * 1536 + ks * 8 + 2 * qc);
            qa[mi][ks][0] = u0.x; qa[mi][ks][1] = u1.x;
            qa[mi][ks][2] = u0.y; qa[mi][ks][3] = u1.y;
        }

    float o[2][8][4];
    float m[2][2], l[2][2];
#pragma unroll
    for (int mi = 0; mi < 2; mi++) {
        m[mi][0] = m[mi][1] = -INFINITY;
        l[mi][0] = l[mi][1] = 0.0f;
#pragma unroll
        for (int j = 0; j < 8; j++)
#pragma unroll
            for (int c = 0; c < 4; c++) o[mi][j][c] = 0.0f;
    }

    const int jmax = 2 * qt + 1;
    const uint32_t* vtb = vt + ((size_t)((b * HH + h) * 64)) * (LL / 2);

    auto stage = [&](int jt, int s) {
        const uint32_t* kg = qkv + ((size_t)(b * LL + jt * 64)) * 1536 + 512 + h * 32;
#pragma unroll
        for (int i = 0; i < 4; i++) {
            const int q = i * 128 + tid;
            const int r = q >> 3, c = q & 7;
            cp_async16(sm_base + (uint32_t)((OFF_K0 + s * TILE_WORDS + r * AST + c * 4) * 4),
                       kg + (size_t)r * 1536 + c * 4);
        }
#pragma unroll
        for (int i = 0; i < 4; i++) {
            const int q = i * 128 + tid;
            const int r = q >> 3, c = q & 7;
            cp_async16(sm_base + (uint32_t)((OFF_V0 + s * TILE_WORDS + r * AST + c * 4) * 4),
                       vtb + (size_t)r * (LL / 2) + jt * 32 + c * 4);
        }
        cp_commit();
    };

    stage(0, 0);

    for (int jt = 0; jt <= jmax; jt++) {
        const int s = jt & 1;
        __syncthreads();
        if (jt + 1 <= jmax) { stage(jt + 1, s ^ 1); cp_wait<1>(); }
        else                { cp_wait<0>(); }
        __syncthreads();

        const uint32_t* Ks = sm + OFF_K0 + s * TILE_WORDS;
        const uint32_t* Vs = sm + OFF_V0 + s * TILE_WORDS;

        const int wrow_min = qt * 128 + wid * 32;
        const bool tile_dead = (jt * 64) > (wrow_min + 31);

        if (!tile_dead) {
            float sreg[2][8][4];
#pragma unroll
            for (int mi = 0; mi < 2; mi++)
#pragma unroll
                for (int j = 0; j < 8; j++)
#pragma unroll
                    for (int c = 0; c < 4; c++) sreg[mi][j][c] = 0.0f;

#pragma unroll
            for (int ks = 0; ks < 4; ks++) {
#pragma unroll
                for (int j = 0; j < 8; j++) {
                    const uint2 kk = *(const uint2*)&Ks[(j * 8 + qr) * AST + ks * 8 + 2 * qc];
                    mma_f16(sreg[0][j], qa[0][ks], kk.x, kk.y);
                    mma_f16(sreg[1][j], qa[1][ks], kk.x, kk.y);
                }
            }

            if ((jt + 1) * 64 - 1 > wrow_min) {
#pragma unroll
                for (int mi = 0; mi < 2; mi++) {
                    const int r0 = wrow_min + mi * 16 + qr;
#pragma unroll
                    for (int j = 0; j < 8; j++) {
                        const int c0 = jt * 64 + j * 8 + qc * 2;
                        if (c0     > r0)     sreg[mi][j][0] = -INFINITY;
                        if (c0 + 1 > r0)     sreg[mi][j][1] = -INFINITY;
                        if (c0     > r0 + 8) sreg[mi][j][2] = -INFINITY;
                        if (c0 + 1 > r0 + 8) sreg[mi][j][3] = -INFINITY;
                    }
                }
            }

#pragma unroll
            for (int mi = 0; mi < 2; mi++) {
                float mt0 = -INFINITY, mt1 = -INFINITY;
#pragma unroll
                for (int j = 0; j < 8; j++) {
                    mt0 = fmaxf(mt0, fmaxf(sreg[mi][j][0], sreg[mi][j][1]));
                    mt1 = fmaxf(mt1, fmaxf(sreg[mi][j][2], sreg[mi][j][3]));
                }
#pragma unroll
                for (int off = 1; off <= 2; off <<= 1) {
                    mt0 = fmaxf(mt0, __shfl_xor_sync(0xffffffffu, mt0, off));
                    mt1 = fmaxf(mt1, __shfl_xor_sync(0xffffffffu, mt1, off));
                }
                const float mn0 = fmaxf(m[mi][0], mt0);
                const float mn1 = fmaxf(m[mi][1], mt1);
                const float al0 = exp2f(m[mi][0] - mn0);
                const float al1 = exp2f(m[mi][1] - mn1);
                m[mi][0] = mn0; m[mi][1] = mn1;
                float rs0 = 0.0f, rs1 = 0.0f;
#pragma unroll
                for (int j = 0; j < 8; j++) {
                    sreg[mi][j][0] = exp2f(sreg[mi][j][0] - mn0);
                    sreg[mi][j][1] = exp2f(sreg[mi][j][1] - mn0);
                    sreg[mi][j][2] = exp2f(sreg[mi][j][2] - mn1);
                    sreg[mi][j][3] = exp2f(sreg[mi][j][3] - mn1);
                    rs0 += sreg[mi][j][0] + sreg[mi][j][1];
                    rs1 += sreg[mi][j][2] + sreg[mi][j][3];
                }
#pragma unroll
                for (int off = 1; off <= 2; off <<= 1) {
                    rs0 += __shfl_xor_sync(0xffffffffu, rs0, off);
                    rs1 += __shfl_xor_sync(0xffffffffu, rs1, off);
                }
                l[mi][0] = l[mi][0] * al0 + rs0;
                l[mi][1] = l[mi][1] * al1 + rs1;
#pragma unroll
                for (int j = 0; j < 8; j++) {
                    o[mi][j][0] *= al0; o[mi][j][1] *= al0;
                    o[mi][j][2] *= al1; o[mi][j][3] *= al1;
                }
            }

#pragma unroll
            for (int ks = 0; ks < 4; ks++) {
                uint32_t pa0[4], pa1[4];
                pa0[0] = pack_f16x2(sreg[0][2 * ks][0],     sreg[0][2 * ks][1]);
                pa0[1] = pack_f16x2(sreg[0][2 * ks][2],     sreg[0][2 * ks][3]);
                pa0[2] = pack_f16x2(sreg[0][2 * ks + 1][0], sreg[0][2 * ks + 1][1]);
                pa0[3] = pack_f16x2(sreg[0][2 * ks + 1][2], sreg[0][2 * ks + 1][3]);
                pa1[0] = pack_f16x2(sreg[1][2 * ks][0],     sreg[1][2 * ks][1]);
                pa1[1] = pack_f16x2(sreg[1][2 * ks][2],     sreg[1][2 * ks][3]);
                pa1[2] = pack_f16x2(sreg[1][2 * ks + 1][0], sreg[1][2 * ks + 1][1]);
                pa1[3] = pack_f16x2(sreg[1][2 * ks + 1][2], sreg[1][2 * ks + 1][3]);
#pragma unroll
                for (int j = 0; j < 8; j++) {
                    const uint2 vv = *(const uint2*)&Vs[(j * 8 + qr) * AST + ks * 8 + 2 * qc];
                    mma_f16(o[0][j], pa0, vv.x, vv.y);
                    mma_f16(o[1][j], pa1, vv.x, vv.y);
                }
            }
        }
    }

    // epilogue: att feeds GEMM0's A operand -> perm32 word layout per h-block.
    const int orow0 = b * LL + qt * 128 + wid * 32;
#pragma unroll
    for (int mi = 0; mi < 2; mi++) {
        const float inv0 = 1.0f / l[mi][0];
        const float inv1 = 1.0f / l[mi][1];
        const size_t r0 = (size_t)(orow0 + mi * 16 + qr) * 512;
#pragma unroll
        for (int j = 0; j < 8; j++) {
            const int wl = j * 4 + qc;                 // 0..31 within head block
            const int wp = h * 32 + perm32(wl);
            att[r0 + wp]             = pack_f16x2(o[mi][j][0] * inv0, o[mi][j][1] * inv0);
            att[r0 + 8 * 512 + wp]   = pack_f16x2(o[mi][j][2] * inv1, o[mi][j][3] * inv1);
        }
    }
}

// ---------------------------------------------------------------------------
extern "C" void kernel_launch(void* const* d_in, const int* in_sizes, int n_in,
                              void* d_out, int out_size)
{
    const float* x    = (const float*)d_in[0];
    const float* Wqkv = (const float*)d_in[1];
    const float* bqkv = (const float*)d_in[2];
    const float* Wout = (const float*)d_in[3];
    const float* bout = (const float*)d_in[4];
    float* outp = (float*)d_out;

    float *qkv = nullptr, *att = nullptr;
    uint32_t *xt = nullptr, *wq = nullptr, *wo = nullptr, *vt = nullptr;
    cudaGetSymbolAddress((void**)&qkv, g_qkv);
    cudaGetSymbolAddress((void**)&att, g_att);
    cudaGetSymbolAddress((void**)&xt, g_xt);
    cudaGetSymbolAddress((void**)&wq, g_wq);
    cudaGetSymbolAddress((void**)&wo, g_wo);
    cudaGetSymbolAddress((void**)&vt, g_vt);

    static bool attr_set = false;
    if (!attr_set) {
        cudaFuncSetAttribute(attn_f16_kernel,
                             cudaFuncAttributeMaxDynamicSharedMemorySize, SMEM_ATTN);
        cudaFuncSetAttribute(gemm_f16<0>,
                             cudaFuncAttributeMaxDynamicSharedMemorySize, SMEM_GEMM);
        cudaFuncSetAttribute(gemm_f16<1>,
                             cudaFuncAttributeMaxDynamicSharedMemorySize, SMEM_GEMM);
        attr_set = true;
    }

    const int M = BB * LL;   // 8192
    const int Kw = DD / 2;   // 512 words

    // prepass: fp32 -> fp16 words, perm32 layout (same perm on both operands)
    {
        int ng = (M * DD) / 32;
        perm_f16_kernel<<<(ng + 255) / 256, 256>>>(x, xt, M, DD);
        ng = (3 * DD * DD) / 32;
        perm_f16_kernel<<<(ng + 255) / 256, 256>>>(Wqkv, wq, 3 * DD, DD);
        ng = (DD * DD) / 32;
        perm_f16_kernel<<<(ng + 255) / 256, 256>>>(Wout, wo, DD, DD);
    }

    // 1) QKV projection (fp16 words out; Q scaled; Q,K pos8, V linear)
    {
        dim3 grid((3 * DD) / 128, M / 128);
        gemm_f16<1><<<grid, 128, SMEM_GEMM>>>(xt, wq, bqkv, qkv, M, 3 * DD, Kw);
    }

    // 1b) V transpose -> [(b,h,hd)][seq-pairs]
    {
        dim3 grid(BB * HH, LL / 64);
        transpose_v_kernel<<<grid, 128>>>(qkv, vt);
    }

    // 2) causal attention (att written in perm32 layout)
    {
        dim3 grid(LL / 128, HH, BB);
        attn_f16_kernel<<<grid, 128, SMEM_ATTN>>>(qkv, vt, att);
    }

    // 3) output projection (fp32 out)
    {
        dim3 grid(DD / 128, M / 128);
        gemm_f16<0><<<grid, 128, SMEM_GEMM>>>((const uint32_t*)att, wo, bout, outp,
                                              M, DD, Kw);
    }
}

// round 12
// speedup vs baseline: 1.0714x; 1.0672x over previous
#include <cuda_runtime.h>
#include <math.h>
#include <stdint.h>

#define BB 4
#define LL 2048
#define DD 1024
#define HH 16
#define HD 64

// Q prescale: 1/sqrt(64) * log2(e) -> softmax in exp2 domain.
#define QSCALE 0.1803368801111204f

// Scratch (device globals). All fp16 payloads stored as packed uint32 words.
__device__ float    g_qkv[(size_t)BB * LL * 3 * DD];       // fp16 words [M][1536]
__device__ float    g_att[(size_t)BB * LL * DD];           // fp16 words [M][512]
__device__ uint32_t g_xt  [(size_t)BB * LL * DD];          // x fp16 words [M][512]
__device__ uint32_t g_wq  [(size_t)3 * DD * DD];           // Wqkv fp16 words [3072][512]
__device__ uint32_t g_wo  [(size_t)DD * DD];               // Wout fp16 words [1024][512]
__device__ uint32_t g_vt  [(size_t)BB * HH * HD * (LL/2)]; // V^T fp16 words [(b,h,hd)][1024]

// pos8 on word index within an 8-word (16-elem) group: i<4 -> 2i, else 2i-7.
__device__ __host__ __forceinline__ int pos8(int i) {
    return (i < 4) ? (i << 1) : ((i << 1) - 7);
}

__device__ __forceinline__ uint32_t pack_f16x2(float lo, float hi) {
    uint32_t r;
    asm("cvt.rn.f16x2.f32 %0, %1, %2;" : "=r"(r) : "f"(hi), "f"(lo));
    return r;
}

__device__ __forceinline__ void cp_async16(uint32_t smem_addr, const void* gptr) {
    asm volatile("cp.async.cg.shared.global [%0], [%1], 16;\n"
                 :: "r"(smem_addr), "l"(gptr));
}
__device__ __forceinline__ void cp_commit() {
    asm volatile("cp.async.commit_group;\n" ::: "memory");
}
template <int N>
__device__ __forceinline__ void cp_wait() {
    asm volatile("cp.async.wait_group %0;\n" :: "n"(N) : "memory");
}

// m16n8k16 f16 mma, f32 acc.
__device__ __forceinline__ void mma_f16(float* d, const uint32_t* a,
                                        uint32_t b0, uint32_t b1) {
    asm volatile(
        "mma.sync.aligned.m16n8k16.row.col.f32.f16.f16.f32 "
        "{%0,%1,%2,%3}, {%4,%5,%6,%7}, {%8,%9}, {%0,%1,%2,%3};\n"
        : "+f"(d[0]), "+f"(d[1]), "+f"(d[2]), "+f"(d[3])
        : "r"(a[0]), "r"(a[1]), "r"(a[2]), "r"(a[3]), "r"(b0), "r"(b1));
}

// ---------------------------------------------------------------------------
// Prepass: fp32 -> fp16 words, word index pos8-permuted within 16-elem groups.
// ---------------------------------------------------------------------------
__global__ void perm_f16_kernel(const float* __restrict__ in,
                                uint32_t* __restrict__ out, int rows, int cols) {
    int gid = blockIdx.x * blockDim.x + threadIdx.x;
    const int gpr = cols >> 4;
    if (gid >= rows * gpr) return;
    const int r = gid / gpr;
    const int gk = gid - r * gpr;
    const float* ip = in + (size_t)r * cols + gk * 16;
    uint32_t* op = out + (size_t)r * (cols >> 1) + gk * 8;
    float e[16];
#pragma unroll
    for (int i = 0; i < 16; i += 4) {
        float4 v = *(const float4*)(ip + i);
        e[i] = v.x; e[i + 1] = v.y; e[i + 2] = v.z; e[i + 3] = v.w;
    }
#pragma unroll
    for (int i = 0; i < 8; i++)
        op[pos8(i)] = pack_f16x2(e[2 * i], e[2 * i + 1]);
}

// ---------------------------------------------------------------------------
// fp16 GEMM (mma.sync m16n8k16), C = A @ W^T + bias.
// OCCUPANCY BUILD: block tile 128x64, 4 warps (2x2), warp tile 64x32
// (acc = 64 regs) -> ~120 regs, 4 CTAs/SM = 4 warps/SMSP (matches the
// attention kernel's config, which empirically saturates the HMMA pipe).
// kTile 16 words (32 elems), 3-stage cp.async, stride-24 padded rows
// (linear base+imm LDS.64 addressing, conflict-free — proven in R8).
// MODE 0: fp32 out + bias. MODE 1: fp16 words out, Q cols scaled, Q/K pos8.
// ---------------------------------------------------------------------------
#define GST 24
#define ABUF (128 * GST)                 // A words per stage
#define BBUF (64 * GST)                  // B words per stage
#define STGW (ABUF + BBUF)               // 4608 words per stage
#define SMEM_GEMM (3 * STGW * 4)         // 55296 B

template <int MODE>
__global__ __launch_bounds__(128, 4) void gemm_f16(
    const uint32_t* __restrict__ A, const uint32_t* __restrict__ W,
    const float* __restrict__ bias, float* __restrict__ C,
    int M, int N, int Kw)
{
    extern __shared__ uint32_t gsm[];   // per stage: A[128*24] | W[64*24]

    const int tid = threadIdx.x;
    const int lane = tid & 31;
    const int ww = tid >> 5;
    const int wr = ww >> 1;          // 0..1 (64-row band)
    const int wc = ww & 1;           // 0..1 (32-col band)
    const int qr = lane >> 2;
    const int qc = lane & 3;
    const int bm = blockIdx.y * 128;
    const int bn = blockIdx.x * 64;

    float acc[4][4][4];
#pragma unroll
    for (int i = 0; i < 4; i++)
#pragma unroll
        for (int j = 0; j < 4; j++)
#pragma unroll
            for (int c = 0; c < 4; c++) acc[i][j][c] = 0.0f;

    const uint32_t sm_base = (uint32_t)__cvta_generic_to_shared(gsm);
    const int nkt = Kw / 16;

    auto stage = [&](int kt_idx, int s) {
#pragma unroll
        for (int i = 0; i < 4; i++) {       // A: 512 chunks of 16B
            const int q = i * 128 + tid;
            const int r = q >> 2, c = q & 3;
            cp_async16(sm_base + (uint32_t)((s * STGW + r * GST + c * 4) * 4),
                       A + (size_t)(bm + r) * Kw + kt_idx * 16 + c * 4);
        }
#pragma unroll
        for (int i = 0; i < 2; i++) {       // W: 256 chunks
            const int q = i * 128 + tid;
            const int r = q >> 2, c = q & 3;
            cp_async16(sm_base + (uint32_t)((s * STGW + ABUF + r * GST + c * 4) * 4),
                       W + (size_t)(bn + r) * Kw + kt_idx * 16 + c * 4);
        }
        cp_commit();
    };

    stage(0, 0);
    stage(1, 1);

    int s = 0;
    for (int kt = 0; kt < nkt; kt++) {
        if (kt + 1 < nkt) cp_wait<1>();
        else              cp_wait<0>();
        __syncthreads();
        if (kt + 2 < nkt) {
            int s2 = s + 2; if (s2 >= 3) s2 -= 3;
            stage(kt + 2, s2);
        }

        const uint32_t* As = gsm + s * STGW;
        const uint32_t* Ws = gsm + s * STGW + ABUF;

#pragma unroll
        for (int ks = 0; ks < 16; ks += 8) {   // two k16 steps
            uint32_t aa[4][4], bb[4][2];
#pragma unroll
            for (int mi = 0; mi < 4; mi++) {
                const int m = wr * 64 + mi * 16 + qr;
                const uint2 u0 = *(const uint2*)&As[m * GST + ks + 2 * qc];
                const uint2 u1 = *(const uint2*)&As[(m + 8) * GST + ks + 2 * qc];
                aa[mi][0] = u0.x; aa[mi][1] = u1.x;
                aa[mi][2] = u0.y; aa[mi][3] = u1.y;
            }
#pragma unroll
            for (int ni = 0; ni < 4; ni++) {
                const int n = wc * 32 + ni * 8 + qr;
                const uint2 v = *(const uint2*)&Ws[n * GST + ks + 2 * qc];
                bb[ni][0] = v.x; bb[ni][1] = v.y;
            }
#pragma unroll
            for (int mi = 0; mi < 4; mi++)
#pragma unroll
                for (int ni = 0; ni < 4; ni++)
                    mma_f16(acc[mi][ni], aa[mi], bb[ni][0], bb[ni][1]);
        }
        s++; if (s == 3) s = 0;
    }

#pragma unroll
    for (int mi = 0; mi < 4; mi++) {
        const int row = bm + wr * 64 + mi * 16 + qr;
#pragma unroll
        for (int ni = 0; ni < 4; ni++) {
            const int col = bn + wc * 32 + ni * 8 + qc * 2;
            const float b0 = bias[col], b1 = bias[col + 1];
            float* d = acc[mi][ni];
            float v00 = d[0] + b0, v01 = d[1] + b1;
            float v10 = d[2] + b0, v11 = d[3] + b1;
            if (MODE == 1) {
                const float sc = (col < DD) ? QSCALE : 1.0f;
                v00 *= sc; v01 *= sc; v10 *= sc; v11 *= sc;
                const int w = col >> 1;
                const int wp = (col < 2 * DD) ? ((w & ~7) | pos8(w & 7)) : w;
                uint32_t* C32 = (uint32_t*)C;
                C32[(size_t)row * (N >> 1) + wp]       = pack_f16x2(v00, v01);
                C32[(size_t)(row + 8) * (N >> 1) + wp] = pack_f16x2(v10, v11);
            } else {
                *(float2*)(C + (size_t)row * N + col)       = make_float2(v00, v01);
                *(float2*)(C + (size_t)(row + 8) * N + col) = make_float2(v10, v11);
            }
        }
    }
}

// ---------------------------------------------------------------------------
// V transpose: qkv V section -> g_vt [(b,h,hd)][seq-pairs], seq-words pos8'd.
// ---------------------------------------------------------------------------
__global__ __launch_bounds__(128) void transpose_v_kernel(
    const float* __restrict__ qkvf, uint32_t* __restrict__ vt)
{
    __shared__ uint32_t ts[64][33];
    const int bh = blockIdx.x;
    const int b = bh >> 4, h = bh & 15;
    const int sc = blockIdx.y;
    const int tid = threadIdx.x;

    const uint32_t* vg = (const uint32_t*)qkvf
        + ((size_t)(b * LL + sc * 64)) * 1536 + 1024 + h * 32;
#pragma unroll
    for (int i = 0; i < 16; i++) {
        const int q = i * 128 + tid;
        const int r = q >> 5, c = q & 31;
        ts[r][c] = vg[(size_t)r * 1536 + c];
    }
    __syncthreads();

#pragma unroll
    for (int i = 0; i < 16; i++) {
        const int q = i * 128 + tid;
        const int hd = q >> 5, sw = q & 31;
        const uint32_t w0 = ts[2 * sw][hd >> 1];
        const uint32_t w1 = ts[2 * sw + 1][hd >> 1];
        const uint32_t sh = (hd & 1) * 16;
        const uint32_t val = ((w0 >> sh) & 0xffffu) | (((w1 >> sh) & 0xffffu) << 16);
        const int swp = (sw & ~7) | pos8(sw & 7);
        vt[((size_t)(bh * 64 + hd)) * (LL / 2) + sc * 32 + swp] = val;
    }
}

// ---------------------------------------------------------------------------
// Causal flash attention, fp16 mma (R8/R9 proven, unchanged).
// ---------------------------------------------------------------------------
#define AST 40
#define TILE_WORDS (64 * AST)
#define OFF_K0 0
#define OFF_V0 (2 * TILE_WORDS)
#define SMEM_ATTN (4 * TILE_WORDS * 4)   // 40 KB

__global__ __launch_bounds__(128) void attn_f16_kernel(
    const float* __restrict__ qkvf, const uint32_t* __restrict__ vt,
    float* __restrict__ outf)
{
    extern __shared__ uint32_t sm[];
    const uint32_t* qkv = (const uint32_t*)qkvf;
    uint32_t* att = (uint32_t*)outf;

    const int qt = gridDim.x - 1 - blockIdx.x;
    const int h  = blockIdx.y;
    const int b  = blockIdx.z;

    const int tid = threadIdx.x;
    const int lane = tid & 31;
    const int wid = tid >> 5;
    const int qr = lane >> 2;
    const int qc = lane & 3;

    const uint32_t sm_base = (uint32_t)__cvta_generic_to_shared(sm);

    uint32_t qa[2][4][4];
    const uint32_t* qb = qkv + ((size_t)(b * LL + qt * 128 + wid * 32)) * 1536 + h * 32;
#pragma unroll
    for (int mi = 0; mi < 2; mi++)
#pragma unroll
        for (int ks = 0; ks < 4; ks++) {
            const size_t r0 = (size_t)(mi * 16 + qr) * 1536;
            const uint2 u0 = *(const uint2*)(qb + r0 + ks * 8 + 2 * qc);
            const uint2 u1 = *(const uint2*)(qb + r0 + 8 * 1536 + ks * 8 + 2 * qc);
            qa[mi][ks][0] = u0.x; qa[mi][ks][1] = u1.x;
            qa[mi][ks][2] = u0.y; qa[mi][ks][3] = u1.y;
        }

    float o[2][8][4];
    float m[2][2], l[2][2];
#pragma unroll
    for (int mi = 0; mi < 2; mi++) {
        m[mi][0] = m[mi][1] = -INFINITY;
        l[mi][0] = l[mi][1] = 0.0f;
#pragma unroll
        for (int j = 0; j < 8; j++)
#pragma unroll
            for (int c = 0; c < 4; c++) o[mi][j][c] = 0.0f;
    }

    const int jmax = 2 * qt + 1;
    const uint32_t* vtb = vt + ((size_t)((b * HH + h) * 64)) * (LL / 2);

    auto stage = [&](int jt, int s) {
        const uint32_t* kg = qkv + ((size_t)(b * LL + jt * 64)) * 1536 + 512 + h * 32;
#pragma unroll
        for (int i = 0; i < 4; i++) {
            const int q = i * 128 + tid;
            const int r = q >> 3, c = q & 7;
            cp_async16(sm_base + (uint32_t)((OFF_K0 + s * TILE_WORDS + r * AST + c * 4) * 4),
                       kg + (size_t)r * 1536 + c * 4);
        }
#pragma unroll
        for (int i = 0; i < 4; i++) {
            const int q = i * 128 + tid;
            const int r = q >> 3, c = q & 7;
            cp_async16(sm_base + (uint32_t)((OFF_V0 + s * TILE_WORDS + r * AST + c * 4) * 4),
                       vtb + (size_t)r * (LL / 2) + jt * 32 + c * 4);
        }
        cp_commit();
    };

    stage(0, 0);

    for (int jt = 0; jt <= jmax; jt++) {
        const int s = jt & 1;
        __syncthreads();
        if (jt + 1 <= jmax) { stage(jt + 1, s ^ 1); cp_wait<1>(); }
        else                { cp_wait<0>(); }
        __syncthreads();

        const uint32_t* Ks = sm + OFF_K0 + s * TILE_WORDS;
        const uint32_t* Vs = sm + OFF_V0 + s * TILE_WORDS;

        const int wrow_min = qt * 128 + wid * 32;
        const bool tile_dead = (jt * 64) > (wrow_min + 31);

        if (!tile_dead) {
            float sreg[2][8][4];
#pragma unroll
            for (int mi = 0; mi < 2; mi++)
#pragma unroll
                for (int j = 0; j < 8; j++)
#pragma unroll
                    for (int c = 0; c < 4; c++) sreg[mi][j][c] = 0.0f;

#pragma unroll
            for (int ks = 0; ks < 4; ks++) {
#pragma unroll
                for (int j = 0; j < 8; j++) {
                    const uint2 kk = *(const uint2*)&Ks[(j * 8 + qr) * AST + ks * 8 + 2 * qc];
                    mma_f16(sreg[0][j], qa[0][ks], kk.x, kk.y);
                    mma_f16(sreg[1][j], qa[1][ks], kk.x, kk.y);
                }
            }

            if ((jt + 1) * 64 - 1 > wrow_min) {
#pragma unroll
                for (int mi = 0; mi < 2; mi++) {
                    const int r0 = wrow_min + mi * 16 + qr;
#pragma unroll
                    for (int j = 0; j < 8; j++) {
                        const int c0 = jt * 64 + j * 8 + qc * 2;
                        if (c0     > r0)     sreg[mi][j][0] = -INFINITY;
                        if (c0 + 1 > r0)     sreg[mi][j][1] = -INFINITY;
                        if (c0     > r0 + 8) sreg[mi][j][2] = -INFINITY;
                        if (c0 + 1 > r0 + 8) sreg[mi][j][3] = -INFINITY;
                    }
                }
            }

#pragma unroll
            for (int mi = 0; mi < 2; mi++) {
                float mt0 = -INFINITY, mt1 = -INFINITY;
#pragma unroll
                for (int j = 0; j < 8; j++) {
                    mt0 = fmaxf(mt0, fmaxf(sreg[mi][j][0], sreg[mi][j][1]));
                    mt1 = fmaxf(mt1, fmaxf(sreg[mi][j][2], sreg[mi][j][3]));
                }
#pragma unroll
                for (int off = 1; off <= 2; off <<= 1) {
                    mt0 = fmaxf(mt0, __shfl_xor_sync(0xffffffffu, mt0, off));
                    mt1 = fmaxf(mt1, __shfl_xor_sync(0xffffffffu, mt1, off));
                }
                const float mn0 = fmaxf(m[mi][0], mt0);
                const float mn1 = fmaxf(m[mi][1], mt1);
                const float al0 = exp2f(m[mi][0] - mn0);
                const float al1 = exp2f(m[mi][1] - mn1);
                m[mi][0] = mn0; m[mi][1] = mn1;
                float rs0 = 0.0f, rs1 = 0.0f;
#pragma unroll
                for (int j = 0; j < 8; j++) {
                    sreg[mi][j][0] = exp2f(sreg[mi][j][0] - mn0);
                    sreg[mi][j][1] = exp2f(sreg[mi][j][1] - mn0);
                    sreg[mi][j][2] = exp2f(sreg[mi][j][2] - mn1);
                    sreg[mi][j][3] = exp2f(sreg[mi][j][3] - mn1);
                    rs0 += sreg[mi][j][0] + sreg[mi][j][1];
                    rs1 += sreg[mi][j][2] + sreg[mi][j][3];
                }
#pragma unroll
                for (int off = 1; off <= 2; off <<= 1) {
                    rs0 += __shfl_xor_sync(0xffffffffu, rs0, off);
                    rs1 += __shfl_xor_sync(0xffffffffu, rs1, off);
                }
                l[mi][0] = l[mi][0] * al0 + rs0;
                l[mi][1] = l[mi][1] * al1 + rs1;
#pragma unroll
                for (int j = 0; j < 8; j++) {
                    o[mi][j][0] *= al0; o[mi][j][1] *= al0;
                    o[mi][j][2] *= al1; o[mi][j][3] *= al1;
                }
            }

#pragma unroll
            for (int ks = 0; ks < 4; ks++) {
                uint32_t pa0[4], pa1[4];
                pa0[0] = pack_f16x2(sreg[0][2 * ks][0],     sreg[0][2 * ks][1]);
                pa0[1] = pack_f16x2(sreg[0][2 * ks][2],     sreg[0][2 * ks][3]);
                pa0[2] = pack_f16x2(sreg[0][2 * ks + 1][0], sreg[0][2 * ks + 1][1]);
                pa0[3] = pack_f16x2(sreg[0][2 * ks + 1][2], sreg[0][2 * ks + 1][3]);
                pa1[0] = pack_f16x2(sreg[1][2 * ks][0],     sreg[1][2 * ks][1]);
                pa1[1] = pack_f16x2(sreg[1][2 * ks][2],     sreg[1][2 * ks][3]);
                pa1[2] = pack_f16x2(sreg[1][2 * ks + 1][0], sreg[1][2 * ks + 1][1]);
                pa1[3] = pack_f16x2(sreg[1][2 * ks + 1][2], sreg[1][2 * ks + 1][3]);
#pragma unroll
                for (int j = 0; j < 8; j++) {
                    const uint2 vv = *(const uint2*)&Vs[(j * 8 + qr) * AST + ks * 8 + 2 * qc];
                    mma_f16(o[0][j], pa0, vv.x, vv.y);
                    mma_f16(o[1][j], pa1, vv.x, vv.y);
                }
            }
        }
    }

    const int orow0 = b * LL + qt * 128 + wid * 32;
#pragma unroll
    for (int mi = 0; mi < 2; mi++) {
        const float inv0 = 1.0f / l[mi][0];
        const float inv1 = 1.0f / l[mi][1];
        const size_t r0 = (size_t)(orow0 + mi * 16 + qr) * 512;
#pragma unroll
        for (int j = 0; j < 8; j++) {
            const int wl = j * 4 + qc;
            const int wp = h * 32 + ((wl & ~7) | pos8(wl & 7));
            att[r0 + wp]             = pack_f16x2(o[mi][j][0] * inv0, o[mi][j][1] * inv0);
            att[r0 + 8 * 512 + wp]   = pack_f16x2(o[mi][j][2] * inv1, o[mi][j][3] * inv1);
        }
    }
}

// ---------------------------------------------------------------------------
extern "C" void kernel_launch(void* const* d_in, const int* in_sizes, int n_in,
                              void* d_out, int out_size)
{
    const float* x    = (const float*)d_in[0];
    const float* Wqkv = (const float*)d_in[1];
    const float* bqkv = (const float*)d_in[2];
    const float* Wout = (const float*)d_in[3];
    const float* bout = (const float*)d_in[4];
    float* outp = (float*)d_out;

    float *qkv = nullptr, *att = nullptr;
    uint32_t *xt = nullptr, *wq = nullptr, *wo = nullptr, *vt = nullptr;
    cudaGetSymbolAddress((void**)&qkv, g_qkv);
    cudaGetSymbolAddress((void**)&att, g_att);
    cudaGetSymbolAddress((void**)&xt, g_xt);
    cudaGetSymbolAddress((void**)&wq, g_wq);
    cudaGetSymbolAddress((void**)&wo, g_wo);
    cudaGetSymbolAddress((void**)&vt, g_vt);

    static bool attr_set = false;
    if (!attr_set) {
        cudaFuncSetAttribute(attn_f16_kernel,
                             cudaFuncAttributeMaxDynamicSharedMemorySize, SMEM_ATTN);
        cudaFuncSetAttribute(gemm_f16<0>,
                             cudaFuncAttributeMaxDynamicSharedMemorySize, SMEM_GEMM);
        cudaFuncSetAttribute(gemm_f16<1>,
                             cudaFuncAttributeMaxDynamicSharedMemorySize, SMEM_GEMM);
        attr_set = true;
    }

    const int M = BB * LL;   // 8192
    const int Kw = DD / 2;   // 512 words

    // prepass: fp32 -> fp16 words, pos8 word-perm (same perm on both operands)
    {
        int ng = (M * DD) / 16;
        perm_f16_kernel<<<(ng + 255) / 256, 256>>>(x, xt, M, DD);
        ng = (3 * DD * DD) / 16;
        perm_f16_kernel<<<(ng + 255) / 256, 256>>>(Wqkv, wq, 3 * DD, DD);
        ng = (DD * DD) / 16;
        perm_f16_kernel<<<(ng + 255) / 256, 256>>>(Wout, wo, DD, DD);
    }

    // 1) QKV projection (fp16 words out; Q scaled; Q,K word-perm'd, V linear)
    {
        dim3 grid((3 * DD) / 64, M / 128);
        gemm_f16<1><<<grid, 128, SMEM_GEMM>>>(xt, wq, bqkv, qkv, M, 3 * DD, Kw);
    }

    // 1b) V transpose -> [(b,h,hd)][seq-pairs]
    {
        dim3 grid(BB * HH, LL / 64);
        transpose_v_kernel<<<grid, 128>>>(qkv, vt);
    }

    // 2) causal attention
    {
        dim3 grid(LL / 128, HH, BB);
        attn_f16_kernel<<<grid, 128, SMEM_ATTN>>>(qkv, vt, att);
    }

    // 3) output projection (fp32 out)
    {
        dim3 grid(DD / 64, M / 128);
        gemm_f16<0><<<grid, 128, SMEM_GEMM>>>((const uint32_t*)att, wo, bout, outp,
                                              M, DD, Kw);
    }
}

// round 13
// speedup vs baseline: 1.1520x; 1.0752x over previous
#include <cuda_runtime.h>
#include <math.h>
#include <stdint.h>

#define BB 4
#define LL 2048
#define DD 1024
#define HH 16
#define HD 64

// Q prescale: 1/sqrt(64) * log2(e) -> softmax in exp2 domain.
#define QSCALE 0.1803368801111204f

// Scratch (device globals). All fp16 payloads stored as packed uint32 words.
__device__ float    g_qkv[(size_t)BB * LL * 3 * DD];       // fp16 words [M][1536]
__device__ float    g_att[(size_t)BB * LL * DD];           // fp16 words [M][512] (linear)
__device__ uint32_t g_xt  [(size_t)BB * LL * DD];          // x fp16 words [M][512] (linear)
__device__ uint32_t g_wq  [(size_t)3 * DD * DD];           // Wqkv fp16 words (linear)
__device__ uint32_t g_wo  [(size_t)DD * DD];               // Wout fp16 words (linear)
__device__ uint32_t g_vt  [(size_t)BB * HH * HD * (LL/2)]; // V^T fp16 words [(b,h,hd)][1024]

// pos8 word permutation within an 8-word group — used ONLY for the
// attention-internal Q/K/Vt layouts (plain LDS.64 fragment path there).
__device__ __host__ __forceinline__ int pos8(int i) {
    return (i < 4) ? (i << 1) : ((i << 1) - 7);
}

__device__ __forceinline__ uint32_t pack_f16x2(float lo, float hi) {
    uint32_t r;
    asm("cvt.rn.f16x2.f32 %0, %1, %2;" : "=r"(r) : "f"(hi), "f"(lo));
    return r;
}

__device__ __forceinline__ void cp_async16(uint32_t smem_addr, const void* gptr) {
    asm volatile("cp.async.cg.shared.global [%0], [%1], 16;\n"
                 :: "r"(smem_addr), "l"(gptr));
}
__device__ __forceinline__ void cp_commit() {
    asm volatile("cp.async.commit_group;\n" ::: "memory");
}
template <int N>
__device__ __forceinline__ void cp_wait() {
    asm volatile("cp.async.wait_group %0;\n" :: "n"(N) : "memory");
}

// m16n8k16 f16 mma, f32 acc.
__device__ __forceinline__ void mma_f16(float* d, const uint32_t* a,
                                        uint32_t b0, uint32_t b1) {
    asm volatile(
        "mma.sync.aligned.m16n8k16.row.col.f32.f16.f16.f32 "
        "{%0,%1,%2,%3}, {%4,%5,%6,%7}, {%8,%9}, {%0,%1,%2,%3};\n"
        : "+f"(d[0]), "+f"(d[1]), "+f"(d[2]), "+f"(d[3])
        : "r"(a[0]), "r"(a[1]), "r"(a[2]), "r"(a[3]), "r"(b0), "r"(b1));
}

// ldmatrix x4 (non-transposed), b16.
__device__ __forceinline__ void ldsm_x4(uint32_t addr, uint32_t* r) {
    asm volatile("ldmatrix.sync.aligned.m8n8.x4.shared.b16 {%0,%1,%2,%3}, [%4];"
                 : "=r"(r[0]), "=r"(r[1]), "=r"(r[2]), "=r"(r[3]) : "r"(addr));
}

// ---------------------------------------------------------------------------
// Prepass: fp32 -> fp16 words (linear layout; ldmatrix needs no permutation).
// One thread per 8 floats.
// ---------------------------------------------------------------------------
__global__ void conv_f16_kernel(const float* __restrict__ in,
                                uint32_t* __restrict__ out, int n8) {
    int i = blockIdx.x * blockDim.x + threadIdx.x;
    if (i >= n8) return;
    const float4 v0 = *(const float4*)(in + (size_t)i * 8);
    const float4 v1 = *(const float4*)(in + (size_t)i * 8 + 4);
    uint4 r;
    r.x = pack_f16x2(v0.x, v0.y);
    r.y = pack_f16x2(v0.z, v0.w);
    r.z = pack_f16x2(v1.x, v1.y);
    r.w = pack_f16x2(v1.z, v1.w);
    *(uint4*)(out + (size_t)i * 4) = r;
}

// ---------------------------------------------------------------------------
// fp16 GEMM (mma.sync m16n8k16 + ldmatrix), C = A @ W^T + bias.
// A:[M][Kw], W:[N][Kw] fp16 words, LINEAR k order.
// Block 128x128, 4 warps (2x2), warp 64x64. kTile 32 words (64 elems) =
// 4 k16-steps. 3-stage cp.async, stride-36 rows (ldmatrix phases and cp.async
// store phases both conflict-free: chunk = (r + c) mod 8).
// Fragments via ldmatrix.x4: A 4/step, B 4/step; double-buffered across steps.
// MODE 0: fp32 out + bias.
// MODE 1: fp16 words out; Q cols scaled by QSCALE; Q/K pos8-permuted words
//         (attention's LDS.64 path wants that layout); V linear.
// ---------------------------------------------------------------------------
#define GST 36
#define ABW (128 * GST)                  // A words per stage
#define STGW (2 * ABW)                   // stage words (A then W)
#define SMEM_GEMM (3 * STGW * 4)         // 110592 B

template <int MODE>
__global__ __launch_bounds__(128) void gemm_f16(
    const uint32_t* __restrict__ A, const uint32_t* __restrict__ W,
    const float* __restrict__ bias, float* __restrict__ C,
    int M, int N, int Kw)
{
    extern __shared__ uint32_t gsm[];

    const int tid = threadIdx.x;
    const int lane = tid & 31;
    const int ww = tid >> 5;
    const int wr = ww >> 1;
    const int wc = ww & 1;
    const int qr = lane >> 2;
    const int qc = lane & 3;
    const int bm = blockIdx.y * 128;
    const int bn = blockIdx.x * 128;

    float acc[4][8][4];
#pragma unroll
    for (int i = 0; i < 4; i++)
#pragma unroll
        for (int j = 0; j < 8; j++)
#pragma unroll
            for (int c = 0; c < 4; c++) acc[i][j][c] = 0.0f;

    const uint32_t sm_base = (uint32_t)__cvta_generic_to_shared(gsm);
    const int nkt = Kw / 32;

    // ldmatrix per-lane offsets (bytes), within a stage:
    // A (non-trans x4 covering m16 x k16 for one mi):
    //   lanes 0-15 -> rows m_base+ (lane&15), k-words +0
    //   lanes 16-31 -> same rows, k-words +4
    const uint32_t a_lane = (uint32_t)(((wr * 64 + (lane & 15)) * GST
                                        + (lane >> 4) * 4) * 4);
    // B (non-trans x4 covering two ni blocks x k16):
    //   lanes 0-7: rows n_base+0..7, +0 ; 8-15: same rows, +4
    //   lanes 16-23: rows n_base+8..15, +0 ; 24-31: same, +4
    const uint32_t b_lane = (uint32_t)(((wc * 64 + ((lane >> 4) << 3) + (lane & 7)) * GST
                                        + ((lane >> 3) & 1) * 4) * 4);

    auto stage = [&](int kt_idx, int s) {
#pragma unroll
        for (int i = 0; i < 8; i++) {       // A: 1024 chunks of 16B
            const int q = i * 128 + tid;
            const int r = q >> 3, c = q & 7;
            cp_async16(sm_base + (uint32_t)((s * STGW + r * GST + c * 4) * 4),
                       A + (size_t)(bm + r) * Kw + kt_idx * 32 + c * 4);
        }
#pragma unroll
        for (int i = 0; i < 8; i++) {       // W: 1024 chunks
            const int q = i * 128 + tid;
            const int r = q >> 3, c = q & 7;
            cp_async16(sm_base + (uint32_t)((s * STGW + ABW + r * GST + c * 4) * 4),
                       W + (size_t)(bn + r) * Kw + kt_idx * 32 + c * 4);
        }
        cp_commit();
    };

    stage(0, 0);
    stage(1, 1);

    int s = 0;
    for (int kt = 0; kt < nkt; kt++) {
        if (kt + 1 < nkt) cp_wait<1>();
        else              cp_wait<0>();
        __syncthreads();
        if (kt + 2 < nkt) {
            int s2 = s + 2; if (s2 >= 3) s2 -= 3;
            stage(kt + 2, s2);
        }

        const uint32_t abase = sm_base + (uint32_t)(s * STGW * 4) + a_lane;
        const uint32_t bbase = sm_base + (uint32_t)((s * STGW + ABW) * 4) + b_lane;

        uint32_t aa[2][4][4], bb[2][4][4];

#define LDFRAG(buf, g)                                                         \
        do {                                                                   \
            _Pragma("unroll")                                                  \
            for (int mi = 0; mi < 4; mi++)                                     \
                ldsm_x4(abase + (uint32_t)(mi * 16 * GST * 4 + (g) * 32),      \
                        aa[buf][mi]);                                          \
            _Pragma("unroll")                                                  \
            for (int p = 0; p < 4; p++)                                        \
                ldsm_x4(bbase + (uint32_t)(p * 16 * GST * 4 + (g) * 32),       \
                        bb[buf][p]);                                           \
        } while (0)

        LDFRAG(0, 0);
#pragma unroll
        for (int st = 0; st < 4; st++) {
            const int cur = st & 1;
            if (st < 3) {
                const int nxt = (st + 1) & 1;
                switch (st) {
                    case 0: LDFRAG(nxt, 1); break;
                    case 1: LDFRAG(nxt, 2); break;
                    default: LDFRAG(nxt, 3); break;
                }
            }
#pragma unroll
            for (int mi = 0; mi < 4; mi++)
#pragma unroll
                for (int p = 0; p < 4; p++) {
                    mma_f16(acc[mi][2 * p],     aa[cur][mi], bb[cur][p][0], bb[cur][p][1]);
                    mma_f16(acc[mi][2 * p + 1], aa[cur][mi], bb[cur][p][2], bb[cur][p][3]);
                }
        }
#undef LDFRAG

        s++; if (s == 3) s = 0;
    }

#pragma unroll
    for (int mi = 0; mi < 4; mi++) {
        const int row = bm + wr * 64 + mi * 16 + qr;
#pragma unroll
        for (int ni = 0; ni < 8; ni++) {
            const int col = bn + wc * 64 + ni * 8 + qc * 2;
            const float b0 = bias[col], b1 = bias[col + 1];
            float* d = acc[mi][ni];
            float v00 = d[0] + b0, v01 = d[1] + b1;
            float v10 = d[2] + b0, v11 = d[3] + b1;
            if (MODE == 1) {
                const float sc = (col < DD) ? QSCALE : 1.0f;
                v00 *= sc; v01 *= sc; v10 *= sc; v11 *= sc;
                const int w = col >> 1;
                const int wp = (col < 2 * DD) ? ((w & ~7) | pos8(w & 7)) : w;
                uint32_t* C32 = (uint32_t*)C;
                C32[(size_t)row * (N >> 1) + wp]       = pack_f16x2(v00, v01);
                C32[(size_t)(row + 8) * (N >> 1) + wp] = pack_f16x2(v10, v11);
            } else {
                *(float2*)(C + (size_t)row * N + col)       = make_float2(v00, v01);
                *(float2*)(C + (size_t)(row + 8) * N + col) = make_float2(v10, v11);
            }
        }
    }
}

// ---------------------------------------------------------------------------
// V transpose: qkv V section -> g_vt [(b,h,hd)][seq-pairs], seq-words pos8'd
// (attention's LDS.64 B-fragment path). Unchanged.
// ---------------------------------------------------------------------------
__global__ __launch_bounds__(128) void transpose_v_kernel(
    const float* __restrict__ qkvf, uint32_t* __restrict__ vt)
{
    __shared__ uint32_t ts[64][33];
    const int bh = blockIdx.x;
    const int b = bh >> 4, h = bh & 15;
    const int sc = blockIdx.y;
    const int tid = threadIdx.x;

    const uint32_t* vg = (const uint32_t*)qkvf
        + ((size_t)(b * LL + sc * 64)) * 1536 + 1024 + h * 32;
#pragma unroll
    for (int i = 0; i < 16; i++) {
        const int q = i * 128 + tid;
        const int r = q >> 5, c = q & 31;
        ts[r][c] = vg[(size_t)r * 1536 + c];
    }
    __syncthreads();

#pragma unroll
    for (int i = 0; i < 16; i++) {
        const int q = i * 128 + tid;
        const int hd = q >> 5, sw = q & 31;
        const uint32_t w0 = ts[2 * sw][hd >> 1];
        const uint32_t w1 = ts[2 * sw + 1][hd >> 1];
        const uint32_t sh = (hd & 1) * 16;
        const uint32_t val = ((w0 >> sh) & 0xffffu) | (((w1 >> sh) & 0xffffu) << 16);
        const int swp = (sw & ~7) | pos8(sw & 7);
        vt[((size_t)(bh * 64 + hd)) * (LL / 2) + sc * 32 + swp] = val;
    }
}

// ---------------------------------------------------------------------------
// Causal flash attention, fp16 mma (R8/R9 proven). Epilogue now writes LINEAR
// word layout (GEMM0 consumes via ldmatrix).
// ---------------------------------------------------------------------------
#define AST 40
#define TILE_WORDS (64 * AST)
#define OFF_K0 0
#define OFF_V0 (2 * TILE_WORDS)
#define SMEM_ATTN (4 * TILE_WORDS * 4)   // 40 KB

__global__ __launch_bounds__(128) void attn_f16_kernel(
    const float* __restrict__ qkvf, const uint32_t* __restrict__ vt,
    float* __restrict__ outf)
{
    extern __shared__ uint32_t sm[];
    const uint32_t* qkv = (const uint32_t*)qkvf;
    uint32_t* att = (uint32_t*)outf;

    const int qt = gridDim.x - 1 - blockIdx.x;
    const int h  = blockIdx.y;
    const int b  = blockIdx.z;

    const int tid = threadIdx.x;
    const int lane = tid & 31;
    const int wid = tid >> 5;
    const int qr = lane >> 2;
    const int qc = lane & 3;

    const uint32_t sm_base = (uint32_t)__cvta_generic_to_shared(sm);

    uint32_t qa[2][4][4];
    const uint32_t* qb = qkv + ((size_t)(b * LL + qt * 128 + wid * 32)) * 1536 + h * 32;
#pragma unroll
    for (int mi = 0; mi < 2; mi++)
#pragma unroll
        for (int ks = 0; ks < 4; ks++) {
            const size_t r0 = (size_t)(mi * 16 + qr) * 1536;
            const uint2 u0 = *(const uint2*)(qb + r0 + ks * 8 + 2 * qc);
            const uint2 u1 = *(const uint2*)(qb + r0 + 8 * 1536 + ks * 8 + 2 * qc);
            qa[mi][ks][0] = u0.x; qa[mi][ks][1] = u1.x;
            qa[mi][ks][2] = u0.y; qa[mi][ks][3] = u1.y;
        }

    float o[2][8][4];
    float m[2][2], l[2][2];
#pragma unroll
    for (int mi = 0; mi < 2; mi++) {
        m[mi][0] = m[mi][1] = -INFINITY;
        l[mi][0] = l[mi][1] = 0.0f;
#pragma unroll
        for (int j = 0; j < 8; j++)
#pragma unroll
            for (int c = 0; c < 4; c++) o[mi][j][c] = 0.0f;
    }

    const int jmax = 2 * qt + 1;
    const uint32_t* vtb = vt + ((size_t)((b * HH + h) * 64)) * (LL / 2);

    auto stage = [&](int jt, int s) {
        const uint32_t* kg = qkv + ((size_t)(b * LL + jt * 64)) * 1536 + 512 + h * 32;
#pragma unroll
        for (int i = 0; i < 4; i++) {
            const int q = i * 128 + tid;
            const int r = q >> 3, c = q & 7;
            cp_async16(sm_base + (uint32_t)((OFF_K0 + s * TILE_WORDS + r * AST + c * 4) * 4),
                       kg + (size_t)r * 1536 + c * 4);
        }
#pragma unroll
        for (int i = 0; i < 4; i++) {
            const int q = i * 128 + tid;
            const int r = q >> 3, c = q & 7;
            cp_async16(sm_base + (uint32_t)((OFF_V0 + s * TILE_WORDS + r * AST + c * 4) * 4),
                       vtb + (size_t)r * (LL / 2) + jt * 32 + c * 4);
        }
        cp_commit();
    };

    stage(0, 0);

    for (int jt = 0; jt <= jmax; jt++) {
        const int s = jt & 1;
        __syncthreads();
        if (jt + 1 <= jmax) { stage(jt + 1, s ^ 1); cp_wait<1>(); }
        else                { cp_wait<0>(); }
        __syncthreads();

        const uint32_t* Ks = sm + OFF_K0 + s * TILE_WORDS;
        const uint32_t* Vs = sm + OFF_V0 + s * TILE_WORDS;

        const int wrow_min = qt * 128 + wid * 32;
        const bool tile_dead = (jt * 64) > (wrow_min + 31);

        if (!tile_dead) {
            float sreg[2][8][4];
#pragma unroll
            for (int mi = 0; mi < 2; mi++)
#pragma unroll
                for (int j = 0; j < 8; j++)
#pragma unroll
                    for (int c = 0; c < 4; c++) sreg[mi][j][c] = 0.0f;

#pragma unroll
            for (int ks = 0; ks < 4; ks++) {
#pragma unroll
                for (int j = 0; j < 8; j++) {
                    const uint2 kk = *(const uint2*)&Ks[(j * 8 + qr) * AST + ks * 8 + 2 * qc];
                    mma_f16(sreg[0][j], qa[0][ks], kk.x, kk.y);
                    mma_f16(sreg[1][j], qa[1][ks], kk.x, kk.y);
                }
            }

            if ((jt + 1) * 64 - 1 > wrow_min) {
#pragma unroll
                for (int mi = 0; mi < 2; mi++) {
                    const int r0 = wrow_min + mi * 16 + qr;
#pragma unroll
                    for (int j = 0; j < 8; j++) {
                        const int c0 = jt * 64 + j * 8 + qc * 2;
                        if (c0     > r0)     sreg[mi][j][0] = -INFINITY;
                        if (c0 + 1 > r0)     sreg[mi][j][1] = -INFINITY;
                        if (c0     > r0 + 8) sreg[mi][j][2] = -INFINITY;
                        if (c0 + 1 > r0 + 8) sreg[mi][j][3] = -INFINITY;
                    }
                }
            }

#pragma unroll
            for (int mi = 0; mi < 2; mi++) {
                float mt0 = -INFINITY, mt1 = -INFINITY;
#pragma unroll
                for (int j = 0; j < 8; j++) {
                    mt0 = fmaxf(mt0, fmaxf(sreg[mi][j][0], sreg[mi][j][1]));
                    mt1 = fmaxf(mt1, fmaxf(sreg[mi][j][2], sreg[mi][j][3]));
                }
#pragma unroll
                for (int off = 1; off <= 2; off <<= 1) {
                    mt0 = fmaxf(mt0, __shfl_xor_sync(0xffffffffu, mt0, off));
                    mt1 = fmaxf(mt1, __shfl_xor_sync(0xffffffffu, mt1, off));
                }
                const float mn0 = fmaxf(m[mi][0], mt0);
                const float mn1 = fmaxf(m[mi][1], mt1);
                const float al0 = exp2f(m[mi][0] - mn0);
                const float al1 = exp2f(m[mi][1] - mn1);
                m[mi][0] = mn0; m[mi][1] = mn1;
                float rs0 = 0.0f, rs1 = 0.0f;
#pragma unroll
                for (int j = 0; j < 8; j++) {
                    sreg[mi][j][0] = exp2f(sreg[mi][j][0] - mn0);
                    sreg[mi][j][1] = exp2f(sreg[mi][j][1] - mn0);
                    sreg[mi][j][2] = exp2f(sreg[mi][j][2] - mn1);
                    sreg[mi][j][3] = exp2f(sreg[mi][j][3] - mn1);
                    rs0 += sreg[mi][j][0] + sreg[mi][j][1];
                    rs1 += sreg[mi][j][2] + sreg[mi][j][3];
                }
#pragma unroll
                for (int off = 1; off <= 2; off <<= 1) {
                    rs0 += __shfl_xor_sync(0xffffffffu, rs0, off);
                    rs1 += __shfl_xor_sync(0xffffffffu, rs1, off);
                }
                l[mi][0] = l[mi][0] * al0 + rs0;
                l[mi][1] = l[mi][1] * al1 + rs1;
#pragma unroll
                for (int j = 0; j < 8; j++) {
                    o[mi][j][0] *= al0; o[mi][j][1] *= al0;
                    o[mi][j][2] *= al1; o[mi][j][3] *= al1;
                }
            }

#pragma unroll
            for (int ks = 0; ks < 4; ks++) {
                uint32_t pa0[4], pa1[4];
                pa0[0] = pack_f16x2(sreg[0][2 * ks][0],     sreg[0][2 * ks][1]);
                pa0[1] = pack_f16x2(sreg[0][2 * ks][2],     sreg[0][2 * ks][3]);
                pa0[2] = pack_f16x2(sreg[0][2 * ks + 1][0], sreg[0][2 * ks + 1][1]);
                pa0[3] = pack_f16x2(sreg[0][2 * ks + 1][2], sreg[0][2 * ks + 1][3]);
                pa1[0] = pack_f16x2(sreg[1][2 * ks][0],     sreg[1][2 * ks][1]);
                pa1[1] = pack_f16x2(sreg[1][2 * ks][2],     sreg[1][2 * ks][3]);
                pa1[2] = pack_f16x2(sreg[1][2 * ks + 1][0], sreg[1][2 * ks + 1][1]);
                pa1[3] = pack_f16x2(sreg[1][2 * ks + 1][2], sreg[1][2 * ks + 1][3]);
#pragma unroll
                for (int j = 0; j < 8; j++) {
                    const uint2 vv = *(const uint2*)&Vs[(j * 8 + qr) * AST + ks * 8 + 2 * qc];
                    mma_f16(o[0][j], pa0, vv.x, vv.y);
                    mma_f16(o[1][j], pa1, vv.x, vv.y);
                }
            }
        }
    }

    // epilogue: LINEAR word layout (GEMM0 uses ldmatrix)
    const int orow0 = b * LL + qt * 128 + wid * 32;
#pragma unroll
    for (int mi = 0; mi < 2; mi++) {
        const float inv0 = 1.0f / l[mi][0];
        const float inv1 = 1.0f / l[mi][1];
        const size_t r0 = (size_t)(orow0 + mi * 16 + qr) * 512;
#pragma unroll
        for (int j = 0; j < 8; j++) {
            const int wp = h * 32 + j * 4 + qc;
            att[r0 + wp]           = pack_f16x2(o[mi][j][0] * inv0, o[mi][j][1] * inv0);
            att[r0 + 8 * 512 + wp] = pack_f16x2(o[mi][j][2] * inv1, o[mi][j][3] * inv1);
        }
    }
}

// ---------------------------------------------------------------------------
extern "C" void kernel_launch(void* const* d_in, const int* in_sizes, int n_in,
                              void* d_out, int out_size)
{
    const float* x    = (const float*)d_in[0];
    const float* Wqkv = (const float*)d_in[1];
    const float* bqkv = (const float*)d_in[2];
    const float* Wout = (const float*)d_in[3];
    const float* bout = (const float*)d_in[4];
    float* outp = (float*)d_out;

    float *qkv = nullptr, *att = nullptr;
    uint32_t *xt = nullptr, *wq = nullptr, *wo = nullptr, *vt = nullptr;
    cudaGetSymbolAddress((void**)&qkv, g_qkv);
    cudaGetSymbolAddress((void**)&att, g_att);
    cudaGetSymbolAddress((void**)&xt, g_xt);
    cudaGetSymbolAddress((void**)&wq, g_wq);
    cudaGetSymbolAddress((void**)&wo, g_wo);
    cudaGetSymbolAddress((void**)&vt, g_vt);

    static bool attr_set = false;
    if (!attr_set) {
        cudaFuncSetAttribute(attn_f16_kernel,
                             cudaFuncAttributeMaxDynamicSharedMemorySize, SMEM_ATTN);
        cudaFuncSetAttribute(gemm_f16<0>,
                             cudaFuncAttributeMaxDynamicSharedMemorySize, SMEM_GEMM);
        cudaFuncSetAttribute(gemm_f16<1>,
                             cudaFuncAttributeMaxDynamicSharedMemorySize, SMEM_GEMM);
        attr_set = true;
    }

    const int M = BB * LL;   // 8192
    const int Kw = DD / 2;   // 512 words

    // prepass: plain fp32 -> fp16 (linear; ldmatrix handles lane distribution)
    {
        int n8 = (M * DD) / 8;
        conv_f16_kernel<<<(n8 + 255) / 256, 256>>>(x, xt, n8);
        n8 = (3 * DD * DD) / 8;
        conv_f16_kernel<<<(n8 + 255) / 256, 256>>>(Wqkv, wq, n8);
        n8 = (DD * DD) / 8;
        conv_f16_kernel<<<(n8 + 255) / 256, 256>>>(Wout, wo, n8);
    }

    // 1) QKV projection (fp16 words out; Q scaled; Q/K pos8, V linear)
    {
        dim3 grid((3 * DD) / 128, M / 128);
        gemm_f16<1><<<grid, 128, SMEM_GEMM>>>(xt, wq, bqkv, qkv, M, 3 * DD, Kw);
    }

    // 1b) V transpose -> [(b,h,hd)][seq-pairs]
    {
        dim3 grid(BB * HH, LL / 64);
        transpose_v_kernel<<<grid, 128>>>(qkv, vt);
    }

    // 2) causal attention (att written linear)
    {
        dim3 grid(LL / 128, HH, BB);
        attn_f16_kernel<<<grid, 128, SMEM_ATTN>>>(qkv, vt, att);
    }

    // 3) output projection (fp32 out)
    {
        dim3 grid(DD / 128, M / 128);
        gemm_f16<0><<<grid, 128, SMEM_GEMM>>>((const uint32_t*)att, wo, bout, outp,
                                              M, DD, Kw);
    }
}

// round 14
// speedup vs baseline: 1.1785x; 1.0231x over previous
#include <cuda_runtime.h>
#include <math.h>
#include <stdint.h>

#define BB 4
#define LL 2048
#define DD 1024
#define HH 16
#define HD 64

// Q prescale: 1/sqrt(64) * log2(e) -> softmax in exp2 domain.
#define QSCALE 0.1803368801111204f

// Scratch (device globals). All fp16 payloads stored as packed uint32 words.
__device__ float    g_qkv[(size_t)BB * LL * 3 * DD];       // fp16 words [M][1536]
__device__ float    g_att[(size_t)BB * LL * DD];           // fp16 words [M][512] (linear)
__device__ uint32_t g_xt  [(size_t)BB * LL * DD];          // x fp16 words (linear)
__device__ uint32_t g_wq  [(size_t)3 * DD * DD];           // Wqkv fp16 words (linear)
__device__ uint32_t g_wo  [(size_t)DD * DD];               // Wout fp16 words (linear)
__device__ uint32_t g_vt  [(size_t)BB * HH * HD * (LL/2)]; // V^T fp16 words [(b,h,hd)][1024]

// pos8 word permutation within an 8-word group — attention-internal layouts only.
__device__ __host__ __forceinline__ int pos8(int i) {
    return (i < 4) ? (i << 1) : ((i << 1) - 7);
}

__device__ __forceinline__ uint32_t pack_f16x2(float lo, float hi) {
    uint32_t r;
    asm("cvt.rn.f16x2.f32 %0, %1, %2;" : "=r"(r) : "f"(hi), "f"(lo));
    return r;
}

__device__ __forceinline__ void cp_async16(uint32_t smem_addr, const void* gptr) {
    asm volatile("cp.async.cg.shared.global [%0], [%1], 16;\n"
                 :: "r"(smem_addr), "l"(gptr));
}
__device__ __forceinline__ void cp_commit() {
    asm volatile("cp.async.commit_group;\n" ::: "memory");
}
template <int N>
__device__ __forceinline__ void cp_wait() {
    asm volatile("cp.async.wait_group %0;\n" :: "n"(N) : "memory");
}

// m16n8k16 f16 mma, f32 acc.
__device__ __forceinline__ void mma_f16(float* d, const uint32_t* a,
                                        uint32_t b0, uint32_t b1) {
    asm volatile(
        "mma.sync.aligned.m16n8k16.row.col.f32.f16.f16.f32 "
        "{%0,%1,%2,%3}, {%4,%5,%6,%7}, {%8,%9}, {%0,%1,%2,%3};\n"
        : "+f"(d[0]), "+f"(d[1]), "+f"(d[2]), "+f"(d[3])
        : "r"(a[0]), "r"(a[1]), "r"(a[2]), "r"(a[3]), "r"(b0), "r"(b1));
}

// ldmatrix x4 (non-transposed), b16.
__device__ __forceinline__ void ldsm_x4(uint32_t addr, uint32_t* r) {
    asm volatile("ldmatrix.sync.aligned.m8n8.x4.shared.b16 {%0,%1,%2,%3}, [%4];"
                 : "=r"(r[0]), "=r"(r[1]), "=r"(r[2]), "=r"(r[3]) : "r"(addr));
}

// ---------------------------------------------------------------------------
// Prepass: fp32 -> fp16 words (linear layout).
// ---------------------------------------------------------------------------
__global__ void conv_f16_kernel(const float* __restrict__ in,
                                uint32_t* __restrict__ out, int n8) {
    int i = blockIdx.x * blockDim.x + threadIdx.x;
    if (i >= n8) return;
    const float4 v0 = *(const float4*)(in + (size_t)i * 8);
    const float4 v1 = *(const float4*)(in + (size_t)i * 8 + 4);
    uint4 r;
    r.x = pack_f16x2(v0.x, v0.y);
    r.y = pack_f16x2(v0.z, v0.w);
    r.z = pack_f16x2(v1.x, v1.y);
    r.w = pack_f16x2(v1.z, v1.w);
    *(uint4*)(out + (size_t)i * 4) = r;
}

// ---------------------------------------------------------------------------
// fp16 GEMM (mma.sync m16n8k16 + ldmatrix), C = A @ W^T + bias.
// OCCUPANCY x LDSM BUILD: block 128x64, 4 warps (2x2), warp 64x32 (acc=64
// regs), kTile 32 words, 2-stage cp.async, stride-36 rows (LDSM + cp.async
// phases conflict-free: chunk = (r + c) mod 8). Single-buffered LDSM frags;
// latency hidden cross-warp at 4 CTAs/SM (launch_bounds(128,4)).
// MODE 0: fp32 out + bias. MODE 1: fp16 out, Q cols scaled, Q/K pos8, V linear.
// ---------------------------------------------------------------------------
#define GST 36
#define ABW (128 * GST)                  // A words per stage
#define WBW (64 * GST)                   // W words per stage
#define STGW (ABW + WBW)                 // 6912 words per stage
#define SMEM_GEMM (2 * STGW * 4)         // 55296 B

template <int MODE>
__global__ __launch_bounds__(128, 4) void gemm_f16(
    const uint32_t* __restrict__ A, const uint32_t* __restrict__ W,
    const float* __restrict__ bias, float* __restrict__ C,
    int M, int N, int Kw)
{
    extern __shared__ uint32_t gsm[];

    const int tid = threadIdx.x;
    const int lane = tid & 31;
    const int ww = tid >> 5;
    const int wr = ww >> 1;          // 0..1 (64-row band)
    const int wc = ww & 1;           // 0..1 (32-col band)
    const int qr = lane >> 2;
    const int qc = lane & 3;
    const int bm = blockIdx.y * 128;
    const int bn = blockIdx.x * 64;

    float acc[4][4][4];
#pragma unroll
    for (int i = 0; i < 4; i++)
#pragma unroll
        for (int j = 0; j < 4; j++)
#pragma unroll
            for (int c = 0; c < 4; c++) acc[i][j][c] = 0.0f;

    const uint32_t sm_base = (uint32_t)__cvta_generic_to_shared(gsm);
    const int nkt = Kw / 32;

    // ldmatrix per-lane byte offsets within a stage:
    const uint32_t a_lane = (uint32_t)(((wr * 64 + (lane & 15)) * GST
                                        + (lane >> 4) * 4) * 4);
    const uint32_t b_lane = (uint32_t)(((wc * 32 + ((lane >> 4) << 3) + (lane & 7)) * GST
                                        + ((lane >> 3) & 1) * 4) * 4);

    auto stage = [&](int kt_idx, int s) {
#pragma unroll
        for (int i = 0; i < 8; i++) {       // A: 1024 chunks of 16B
            const int q = i * 128 + tid;
            const int r = q >> 3, c = q & 7;
            cp_async16(sm_base + (uint32_t)((s * STGW + r * GST + c * 4) * 4),
                       A + (size_t)(bm + r) * Kw + kt_idx * 32 + c * 4);
        }
#pragma unroll
        for (int i = 0; i < 4; i++) {       // W: 512 chunks
            const int q = i * 128 + tid;
            const int r = q >> 3, c = q & 7;
            cp_async16(sm_base + (uint32_t)((s * STGW + ABW + r * GST + c * 4) * 4),
                       W + (size_t)(bn + r) * Kw + kt_idx * 32 + c * 4);
        }
        cp_commit();
    };

    stage(0, 0);

    for (int kt = 0; kt < nkt; kt++) {
        const int s = kt & 1;
        __syncthreads();   // all warps done reading buffer s^1 (iter kt-1)
        if (kt + 1 < nkt) { stage(kt + 1, s ^ 1); cp_wait<1>(); }
        else              { cp_wait<0>(); }
        __syncthreads();

        const uint32_t abase = sm_base + (uint32_t)(s * STGW * 4) + a_lane;
        const uint32_t bbase = sm_base + (uint32_t)((s * STGW + ABW) * 4) + b_lane;

#pragma unroll
        for (int st = 0; st < 4; st++) {
            uint32_t aa[4][4], bb[2][4];
#pragma unroll
            for (int mi = 0; mi < 4; mi++)
                ldsm_x4(abase + (uint32_t)(mi * 16 * GST * 4 + st * 32), aa[mi]);
#pragma unroll
            for (int p = 0; p < 2; p++)
                ldsm_x4(bbase + (uint32_t)(p * 16 * GST * 4 + st * 32), bb[p]);

#pragma unroll
            for (int mi = 0; mi < 4; mi++)
#pragma unroll
                for (int p = 0; p < 2; p++) {
                    mma_f16(acc[mi][2 * p],     aa[mi], bb[p][0], bb[p][1]);
                    mma_f16(acc[mi][2 * p + 1], aa[mi], bb[p][2], bb[p][3]);
                }
        }
    }

#pragma unroll
    for (int mi = 0; mi < 4; mi++) {
        const int row = bm + wr * 64 + mi * 16 + qr;
#pragma unroll
        for (int ni = 0; ni < 4; ni++) {
            const int col = bn + wc * 32 + ni * 8 + qc * 2;
            const float b0 = bias[col], b1 = bias[col + 1];
            float* d = acc[mi][ni];
            float v00 = d[0] + b0, v01 = d[1] + b1;
            float v10 = d[2] + b0, v11 = d[3] + b1;
            if (MODE == 1) {
                const float sc = (col < DD) ? QSCALE : 1.0f;
                v00 *= sc; v01 *= sc; v10 *= sc; v11 *= sc;
                const int w = col >> 1;
                const int wp = (col < 2 * DD) ? ((w & ~7) | pos8(w & 7)) : w;
                uint32_t* C32 = (uint32_t*)C;
                C32[(size_t)row * (N >> 1) + wp]       = pack_f16x2(v00, v01);
                C32[(size_t)(row + 8) * (N >> 1) + wp] = pack_f16x2(v10, v11);
            } else {
                *(float2*)(C + (size_t)row * N + col)       = make_float2(v00, v01);
                *(float2*)(C + (size_t)(row + 8) * N + col) = make_float2(v10, v11);
            }
        }
    }
}

// ---------------------------------------------------------------------------
// V transpose: qkv V section -> g_vt [(b,h,hd)][seq-pairs], seq-words pos8'd.
// ---------------------------------------------------------------------------
__global__ __launch_bounds__(128) void transpose_v_kernel(
    const float* __restrict__ qkvf, uint32_t* __restrict__ vt)
{
    __shared__ uint32_t ts[64][33];
    const int bh = blockIdx.x;
    const int b = bh >> 4, h = bh & 15;
    const int sc = blockIdx.y;
    const int tid = threadIdx.x;

    const uint32_t* vg = (const uint32_t*)qkvf
        + ((size_t)(b * LL + sc * 64)) * 1536 + 1024 + h * 32;
#pragma unroll
    for (int i = 0; i < 16; i++) {
        const int q = i * 128 + tid;
        const int r = q >> 5, c = q & 31;
        ts[r][c] = vg[(size_t)r * 1536 + c];
    }
    __syncthreads();

#pragma unroll
    for (int i = 0; i < 16; i++) {
        const int q = i * 128 + tid;
        const int hd = q >> 5, sw = q & 31;
        const uint32_t w0 = ts[2 * sw][hd >> 1];
        const uint32_t w1 = ts[2 * sw + 1][hd >> 1];
        const uint32_t sh = (hd & 1) * 16;
        const uint32_t val = ((w0 >> sh) & 0xffffu) | (((w1 >> sh) & 0xffffu) << 16);
        const int swp = (sw & ~7) | pos8(sw & 7);
        vt[((size_t)(bh * 64 + hd)) * (LL / 2) + sc * 32 + swp] = val;
    }
}

// ---------------------------------------------------------------------------
// Causal flash attention, fp16 mma (R13 verbatim; epilogue linear).
// ---------------------------------------------------------------------------
#define AST 40
#define TILE_WORDS (64 * AST)
#define OFF_K0 0
#define OFF_V0 (2 * TILE_WORDS)
#define SMEM_ATTN (4 * TILE_WORDS * 4)   // 40 KB

__global__ __launch_bounds__(128) void attn_f16_kernel(
    const float* __restrict__ qkvf, const uint32_t* __restrict__ vt,
    float* __restrict__ outf)
{
    extern __shared__ uint32_t sm[];
    const uint32_t* qkv = (const uint32_t*)qkvf;
    uint32_t* att = (uint32_t*)outf;

    const int qt = gridDim.x - 1 - blockIdx.x;
    const int h  = blockIdx.y;
    const int b  = blockIdx.z;

    const int tid = threadIdx.x;
    const int lane = tid & 31;
    const int wid = tid >> 5;
    const int qr = lane >> 2;
    const int qc = lane & 3;

    const uint32_t sm_base = (uint32_t)__cvta_generic_to_shared(sm);

    uint32_t qa[2][4][4];
    const uint32_t* qb = qkv + ((size_t)(b * LL + qt * 128 + wid * 32)) * 1536 + h * 32;
#pragma unroll
    for (int mi = 0; mi < 2; mi++)
#pragma unroll
        for (int ks = 0; ks < 4; ks++) {
            const size_t r0 = (size_t)(mi * 16 + qr) * 1536;
            const uint2 u0 = *(const uint2*)(qb + r0 + ks * 8 + 2 * qc);
            const uint2 u1 = *(const uint2*)(qb + r0 + 8 * 1536 + ks * 8 + 2 * qc);
            qa[mi][ks][0] = u0.x; qa[mi][ks][1] = u1.x;
            qa[mi][ks][2] = u0.y; qa[mi][ks][3] = u1.y;
        }

    float o[2][8][4];
    float m[2][2], l[2][2];
#pragma unroll
    for (int mi = 0; mi < 2; mi++) {
        m[mi][0] = m[mi][1] = -INFINITY;
        l[mi][0] = l[mi][1] = 0.0f;
#pragma unroll
        for (int j = 0; j < 8; j++)
#pragma unroll
            for (int c = 0; c < 4; c++) o[mi][j][c] = 0.0f;
    }

    const int jmax = 2 * qt + 1;
    const uint32_t* vtb = vt + ((size_t)((b * HH + h) * 64)) * (LL / 2);

    auto stage = [&](int jt, int s) {
        const uint32_t* kg = qkv + ((size_t)(b * LL + jt * 64)) * 1536 + 512 + h * 32;
#pragma unroll
        for (int i = 0; i < 4; i++) {
            const int q = i * 128 + tid;
            const int r = q >> 3, c = q & 7;
            cp_async16(sm_base + (uint32_t)((OFF_K0 + s * TILE_WORDS + r * AST + c * 4) * 4),
                       kg + (size_t)r * 1536 + c * 4);
        }
#pragma unroll
        for (int i = 0; i < 4; i++) {
            const int q = i * 128 + tid;
            const int r = q >> 3, c = q & 7;
            cp_async16(sm_base + (uint32_t)((OFF_V0 + s * TILE_WORDS + r * AST + c * 4) * 4),
                       vtb + (size_t)r * (LL / 2) + jt * 32 + c * 4);
        }
        cp_commit();
    };

    stage(0, 0);

    for (int jt = 0; jt <= jmax; jt++) {
        const int s = jt & 1;
        __syncthreads();
        if (jt + 1 <= jmax) { stage(jt + 1, s ^ 1); cp_wait<1>(); }
        else                { cp_wait<0>(); }
        __syncthreads();

        const uint32_t* Ks = sm + OFF_K0 + s * TILE_WORDS;
        const uint32_t* Vs = sm + OFF_V0 + s * TILE_WORDS;

        const int wrow_min = qt * 128 + wid * 32;
        const bool tile_dead = (jt * 64) > (wrow_min + 31);

        if (!tile_dead) {
            float sreg[2][8][4];
#pragma unroll
            for (int mi = 0; mi < 2; mi++)
#pragma unroll
                for (int j = 0; j < 8; j++)
#pragma unroll
                    for (int c = 0; c < 4; c++) sreg[mi][j][c] = 0.0f;

#pragma unroll
            for (int ks = 0; ks < 4; ks++) {
#pragma unroll
                for (int j = 0; j < 8; j++) {
                    const uint2 kk = *(const uint2*)&Ks[(j * 8 + qr) * AST + ks * 8 + 2 * qc];
                    mma_f16(sreg[0][j], qa[0][ks], kk.x, kk.y);
                    mma_f16(sreg[1][j], qa[1][ks], kk.x, kk.y);
                }
            }

            if ((jt + 1) * 64 - 1 > wrow_min) {
#pragma unroll
                for (int mi = 0; mi < 2; mi++) {
                    const int r0 = wrow_min + mi * 16 + qr;
#pragma unroll
                    for (int j = 0; j < 8; j++) {
                        const int c0 = jt * 64 + j * 8 + qc * 2;
                        if (c0     > r0)     sreg[mi][j][0] = -INFINITY;
                        if (c0 + 1 > r0)     sreg[mi][j][1] = -INFINITY;
                        if (c0     > r0 + 8) sreg[mi][j][2] = -INFINITY;
                        if (c0 + 1 > r0 + 8) sreg[mi][j][3] = -INFINITY;
                    }
                }
            }

#pragma unroll
            for (int mi = 0; mi < 2; mi++) {
                float mt0 = -INFINITY, mt1 = -INFINITY;
#pragma unroll
                for (int j = 0; j < 8; j++) {
                    mt0 = fmaxf(mt0, fmaxf(sreg[mi][j][0], sreg[mi][j][1]));
                    mt1 = fmaxf(mt1, fmaxf(sreg[mi][j][2], sreg[mi][j][3]));
                }
#pragma unroll
                for (int off = 1; off <= 2; off <<= 1) {
                    mt0 = fmaxf(mt0, __shfl_xor_sync(0xffffffffu, mt0, off));
                    mt1 = fmaxf(mt1, __shfl_xor_sync(0xffffffffu, mt1, off));
                }
                const float mn0 = fmaxf(m[mi][0], mt0);
                const float mn1 = fmaxf(m[mi][1], mt1);
                const float al0 = exp2f(m[mi][0] - mn0);
                const float al1 = exp2f(m[mi][1] - mn1);
                m[mi][0] = mn0; m[mi][1] = mn1;
                float rs0 = 0.0f, rs1 = 0.0f;
#pragma unroll
                for (int j = 0; j < 8; j++) {
                    sreg[mi][j][0] = exp2f(sreg[mi][j][0] - mn0);
                    sreg[mi][j][1] = exp2f(sreg[mi][j][1] - mn0);
                    sreg[mi][j][2] = exp2f(sreg[mi][j][2] - mn1);
                    sreg[mi][j][3] = exp2f(sreg[mi][j][3] - mn1);
                    rs0 += sreg[mi][j][0] + sreg[mi][j][1];
                    rs1 += sreg[mi][j][2] + sreg[mi][j][3];
                }
#pragma unroll
                for (int off = 1; off <= 2; off <<= 1) {
                    rs0 += __shfl_xor_sync(0xffffffffu, rs0, off);
                    rs1 += __shfl_xor_sync(0xffffffffu, rs1, off);
                }
                l[mi][0] = l[mi][0] * al0 + rs0;
                l[mi][1] = l[mi][1] * al1 + rs1;
#pragma unroll
                for (int j = 0; j < 8; j++) {
                    o[mi][j][0] *= al0; o[mi][j][1] *= al0;
                    o[mi][j][2] *= al1; o[mi][j][3] *= al1;
                }
            }

#pragma unroll
            for (int ks = 0; ks < 4; ks++) {
                uint32_t pa0[4], pa1[4];
                pa0[0] = pack_f16x2(sreg[0][2 * ks][0],     sreg[0][2 * ks][1]);
                pa0[1] = pack_f16x2(sreg[0][2 * ks][2],     sreg[0][2 * ks][3]);
                pa0[2] = pack_f16x2(sreg[0][2 * ks + 1][0], sreg[0][2 * ks + 1][1]);
                pa0[3] = pack_f16x2(sreg[0][2 * ks + 1][2], sreg[0][2 * ks + 1][3]);
                pa1[0] = pack_f16x2(sreg[1][2 * ks][0],     sreg[1][2 * ks][1]);
                pa1[1] = pack_f16x2(sreg[1][2 * ks][2],     sreg[1][2 * ks][3]);
                pa1[2] = pack_f16x2(sreg[1][2 * ks + 1][0], sreg[1][2 * ks + 1][1]);
                pa1[3] = pack_f16x2(sreg[1][2 * ks + 1][2], sreg[1][2 * ks + 1][3]);
#pragma unroll
                for (int j = 0; j < 8; j++) {
                    const uint2 vv = *(const uint2*)&Vs[(j * 8 + qr) * AST + ks * 8 + 2 * qc];
                    mma_f16(o[0][j], pa0, vv.x, vv.y);
                    mma_f16(o[1][j], pa1, vv.x, vv.y);
                }
            }
        }
    }

    // epilogue: LINEAR word layout (GEMM0 uses ldmatrix)
    const int orow0 = b * LL + qt * 128 + wid * 32;
#pragma unroll
    for (int mi = 0; mi < 2; mi++) {
        const float inv0 = 1.0f / l[mi][0];
        const float inv1 = 1.0f / l[mi][1];
        const size_t r0 = (size_t)(orow0 + mi * 16 + qr) * 512;
#pragma unroll
        for (int j = 0; j < 8; j++) {
            const int wp = h * 32 + j * 4 + qc;
            att[r0 + wp]           = pack_f16x2(o[mi][j][0] * inv0, o[mi][j][1] * inv0);
            att[r0 + 8 * 512 + wp] = pack_f16x2(o[mi][j][2] * inv1, o[mi][j][3] * inv1);
        }
    }
}

// ---------------------------------------------------------------------------
extern "C" void kernel_launch(void* const* d_in, const int* in_sizes, int n_in,
                              void* d_out, int out_size)
{
    const float* x    = (const float*)d_in[0];
    const float* Wqkv = (const float*)d_in[1];
    const float* bqkv = (const float*)d_in[2];
    const float* Wout = (const float*)d_in[3];
    const float* bout = (const float*)d_in[4];
    float* outp = (float*)d_out;

    float *qkv = nullptr, *att = nullptr;
    uint32_t *xt = nullptr, *wq = nullptr, *wo = nullptr, *vt = nullptr;
    cudaGetSymbolAddress((void**)&qkv, g_qkv);
    cudaGetSymbolAddress((void**)&att, g_att);
    cudaGetSymbolAddress((void**)&xt, g_xt);
    cudaGetSymbolAddress((void**)&wq, g_wq);
    cudaGetSymbolAddress((void**)&wo, g_wo);
    cudaGetSymbolAddress((void**)&vt, g_vt);

    static bool attr_set = false;
    if (!attr_set) {
        cudaFuncSetAttribute(attn_f16_kernel,
                             cudaFuncAttributeMaxDynamicSharedMemorySize, SMEM_ATTN);
        cudaFuncSetAttribute(gemm_f16<0>,
                             cudaFuncAttributeMaxDynamicSharedMemorySize, SMEM_GEMM);
        cudaFuncSetAttribute(gemm_f16<1>,
                             cudaFuncAttributeMaxDynamicSharedMemorySize, SMEM_GEMM);
        attr_set = true;
    }

    const int M = BB * LL;   // 8192
    const int Kw = DD / 2;   // 512 words

    // prepass: plain fp32 -> fp16 (linear; ldmatrix handles lane distribution)
    {
        int n8 = (M * DD) / 8;
        conv_f16_kernel<<<(n8 + 255) / 256, 256>>>(x, xt, n8);
        n8 = (3 * DD * DD) / 8;
        conv_f16_kernel<<<(n8 + 255) / 256, 256>>>(Wqkv, wq, n8);
        n8 = (DD * DD) / 8;
        conv_f16_kernel<<<(n8 + 255) / 256, 256>>>(Wout, wo, n8);
    }

    // 1) QKV projection (fp16 words out; Q scaled; Q/K pos8, V linear)
    {
        dim3 grid((3 * DD) / 64, M / 128);
        gemm_f16<1><<<grid, 128, SMEM_GEMM>>>(xt, wq, bqkv, qkv, M, 3 * DD, Kw);
    }

    // 1b) V transpose -> [(b,h,hd)][seq-pairs]
    {
        dim3 grid(BB * HH, LL / 64);
        transpose_v_kernel<<<grid, 128>>>(qkv, vt);
    }

    // 2) causal attention (att written linear)
    {
        dim3 grid(LL / 128, HH, BB);
        attn_f16_kernel<<<grid, 128, SMEM_ATTN>>>(qkv, vt, att);
    }

    // 3) output projection (fp32 out)
    {
        dim3 grid(DD / 64, M / 128);
        gemm_f16<0><<<grid, 128, SMEM_GEMM>>>((const uint32_t*)att, wo, bout, outp,
                                              M, DD, Kw);
    }
}